// round 11
// baseline (speedup 1.0000x reference)
#include <cuda_runtime.h>
#include <cuda_bf16.h>
#include <math.h>
#include <stdint.h>

#define SEQ       2048
#define EMBED     1536
#define NHEADS    12
#define HDIM      128
#define QKV_N     (3 * EMBED)         // 4608
#define K2        (2 * EMBED)         // hi|lo layout width = 3072
#define D2        (HDIM / 2)          // 64
#define EPS       1e-5f
#define ATT_SCALE 0.08838834764831843f   // 1/sqrt(128)

// ---------------- scratch (device globals) ----------------
__device__ __nv_bfloat16 g_Ax   [SEQ * K2];             // x split   [m][hi|lo]
__device__ __nv_bfloat16 g_Actx [SEQ * K2];             // ctx split [m][hi|lo] (written by attn)
__device__ __nv_bfloat16 g_Wtqkv[QKV_N * K2];           // W_qkv^T split  (N x 2K)
__device__ __nv_bfloat16 g_Wtprj[EMBED * K2];           // W_proj^T split (N x 2K)
// attention operands merged hi|lo: [h][s][256] (hi at d, lo at 128+d)
__device__ __nv_bfloat16 g_q2[NHEADS * SEQ * 2 * HDIM];
__device__ __nv_bfloat16 g_k2[NHEADS * SEQ * 2 * HDIM];
__device__ __nv_bfloat16 g_v2[NHEADS * SEQ * 2 * HDIM];

// ============================================================================
// helpers
// ============================================================================
__device__ __forceinline__ uint32_t smem_to_u32(const void* p) {
    uint32_t a;
    asm("{ .reg .u64 t; cvta.to.shared.u64 t, %1; cvt.u32.u64 %0, t; }" : "=r"(a) : "l"(p));
    return a;
}
#define CP_ASYNC16(saddr, gptr) \
    asm volatile("cp.async.cg.shared.global [%0], [%1], 16;" \
        :: "r"(saddr), "l"(gptr) : "memory")
#define CP_COMMIT() asm volatile("cp.async.commit_group;" ::: "memory")
#define CP_WAIT1()  asm volatile("cp.async.wait_group 1;" ::: "memory")

__device__ __forceinline__ void ldm_x4(uint32_t* r, uint32_t addr) {
    asm volatile("ldmatrix.sync.aligned.m8n8.x4.shared.b16 {%0,%1,%2,%3}, [%4];"
        : "=r"(r[0]), "=r"(r[1]), "=r"(r[2]), "=r"(r[3]) : "r"(addr));
}
__device__ __forceinline__ void ldm_x4_trans(uint32_t* r, uint32_t addr) {
    asm volatile("ldmatrix.sync.aligned.m8n8.x4.trans.shared.b16 {%0,%1,%2,%3}, [%4];"
        : "=r"(r[0]), "=r"(r[1]), "=r"(r[2]), "=r"(r[3]) : "r"(addr));
}
__device__ __forceinline__ void mma_bf16(float* d, const uint32_t* a, const uint32_t* b) {
    asm volatile(
        "mma.sync.aligned.m16n8k16.row.col.f32.bf16.bf16.f32 "
        "{%0,%1,%2,%3}, {%4,%5,%6,%7}, {%8,%9}, {%0,%1,%2,%3};"
        : "+f"(d[0]), "+f"(d[1]), "+f"(d[2]), "+f"(d[3])
        : "r"(a[0]), "r"(a[1]), "r"(a[2]), "r"(a[3]), "r"(b[0]), "r"(b[1]));
}
__device__ __forceinline__ uint32_t pack2bf(float lo, float hi) {
    __nv_bfloat162 t = __floats2bfloat162_rn(lo, hi);
    return *(uint32_t*)&t;
}

// ============================================================================
// Split-bf16 conversion kernels (hi|lo 2K layouts)
// ============================================================================
__global__ __launch_bounds__(256) void conv_split_A(
    const float* __restrict__ src, __nv_bfloat16* __restrict__ dst, int M, int K)
{
    int idx = blockIdx.x * 256 + threadIdx.x;
    if (idx >= M * K) return;
    int m = idx / K, k = idx - m * K;
    float x  = src[idx];
    __nv_bfloat16 hi = __float2bfloat16(x);
    __nv_bfloat16 lo = __float2bfloat16(x - __bfloat162float(hi));
    __nv_bfloat16* row = dst + (size_t)m * (2 * K);
    row[k]     = hi;
    row[K + k] = lo;
}

__global__ __launch_bounds__(256) void conv_split_Wt(
    const float* __restrict__ W, __nv_bfloat16* __restrict__ Wt, int K, int N)
{
    __shared__ float tile[32][33];
    int k0 = blockIdx.x * 32, n0 = blockIdx.y * 32;
    int tx = threadIdx.x, ty = threadIdx.y;   // block (32, 8)
#pragma unroll
    for (int r = 0; r < 32; r += 8)
        tile[ty + r][tx] = W[(size_t)(k0 + ty + r) * N + n0 + tx];
    __syncthreads();
#pragma unroll
    for (int r = 0; r < 32; r += 8) {
        int n = n0 + ty + r, k = k0 + tx;
        float x  = tile[tx][ty + r];
        __nv_bfloat16 hi = __float2bfloat16(x);
        __nv_bfloat16 lo = __float2bfloat16(x - __bfloat162float(hi));
        __nv_bfloat16* row = Wt + (size_t)n * (2 * K);
        row[k]     = hi;
        row[K + k] = lo;
    }
}

// ============================================================================
// mma.sync GEMM (shared-operand split): C = A @ Bt^T + bias
// fuse==1 (QKV): epilogue does RMSNorm+RoPE+hi/lo split, writes g_q2/g_k2/g_v2.
// fuse==0 (proj): plain fp32 write with bias.
// ============================================================================
#define MM_BM     128
#define MM_BN     128
#define MM_PADB   144
#define MM_TILEB  (128 * MM_PADB)            // 18432
#define MM_STAGEB (2 * MM_TILEB)             // 36864
#define MM_STAGES 3
#define MM_SMEM   (MM_STAGES * MM_STAGEB)    // 110592
#define EP_PAD    133                        // fp32 epilogue tile row stride

__device__ __forceinline__ void mm_load_tile(
    const __nv_bfloat16* __restrict__ src, int row0, int kk, int chunk,
    uint32_t dstBase, int tid)
{
#pragma unroll
    for (int c2 = 0; c2 < 8; c2++) {
        int idx = c2 * 128 + tid;
        int row = idx >> 3;
        int c16 = idx & 7;           // 0..3 hi, 4..7 lo
        const char* gb = (const char*)(src + (size_t)(row0 + row) * (2 * kk));
        const char* g  = (c16 < 4)
            ? gb + chunk * 64 + c16 * 16
            : gb + (size_t)kk * 2 + chunk * 64 + (c16 - 4) * 16;
        CP_ASYNC16(dstBase + (uint32_t)(row * MM_PADB + c16 * 16), g);
    }
}

__global__ __launch_bounds__(128, 2) void gemm_mma(
    const __nv_bfloat16* __restrict__ A, const __nv_bfloat16* __restrict__ Bt,
    const float* __restrict__ bias, float* __restrict__ C, int N, int kk,
    int fuse,
    const float* __restrict__ cosb, const float* __restrict__ sinb,
    const float* __restrict__ qw,   const float* __restrict__ kw)
{
    extern __shared__ char mmsm[];
    const uint32_t S_u = smem_to_u32(mmsm);

    const int tid    = threadIdx.x;
    const int lane   = tid & 31;
    const int wid    = tid >> 5;
    const int warp_m = wid & 1;
    const int warp_n = wid >> 1;
    const int m0 = blockIdx.y * MM_BM;
    const int n0 = blockIdx.x * MM_BN;
    const int nchunk = kk / 32;        // 48

    float acc[4][8][4];
#pragma unroll
    for (int mt = 0; mt < 4; mt++)
#pragma unroll
        for (int nt = 0; nt < 8; nt++)
#pragma unroll
            for (int q = 0; q < 4; q++) acc[mt][nt][q] = 0.f;

    const uint32_t aFrag = (uint32_t)((warp_m * 64 + (lane & 15)) * MM_PADB + (lane >> 4) * 16);
    const uint32_t bFrag = (uint32_t)((warp_n * 64 + ((lane >> 4) << 3) + (lane & 7)) * MM_PADB
                                      + ((lane >> 3) & 1) * 16);

    mm_load_tile(A,  m0, kk, 0, S_u,             tid);
    mm_load_tile(Bt, n0, kk, 0, S_u + MM_TILEB,  tid);
    CP_COMMIT();
    mm_load_tile(A,  m0, kk, 1, S_u + MM_STAGEB,            tid);
    mm_load_tile(Bt, n0, kk, 1, S_u + MM_STAGEB + MM_TILEB, tid);
    CP_COMMIT();

    int slot = 0;
    for (int c = 0; c < nchunk; ++c) {
        CP_WAIT1();
        __syncthreads();
        if (c + 2 < nchunk) {
            int ns = slot + 2; if (ns >= MM_STAGES) ns -= MM_STAGES;
            mm_load_tile(A,  m0, kk, c + 2, S_u + ns * MM_STAGEB,            tid);
            mm_load_tile(Bt, n0, kk, c + 2, S_u + ns * MM_STAGEB + MM_TILEB, tid);
        }
        CP_COMMIT();

        const uint32_t Au = S_u + slot * MM_STAGEB;
        const uint32_t Bu = Au + MM_TILEB;
#pragma unroll
        for (int ks = 0; ks < 2; ++ks) {
            uint32_t ah[4][4], bh[4][4], xl[4][4];
#pragma unroll
            for (int mt = 0; mt < 4; mt++)
                ldm_x4(ah[mt], Au + aFrag + mt * 16 * MM_PADB + ks * 32);
#pragma unroll
            for (int p = 0; p < 4; p++)
                ldm_x4(bh[p], Bu + bFrag + p * 16 * MM_PADB + ks * 32);
#pragma unroll
            for (int mt = 0; mt < 4; mt++)
#pragma unroll
                for (int p = 0; p < 4; p++) {
                    mma_bf16(acc[mt][2 * p],     ah[mt], bh[p]);
                    mma_bf16(acc[mt][2 * p + 1], ah[mt], bh[p] + 2);
                }
#pragma unroll
            for (int p = 0; p < 4; p++)
                ldm_x4(xl[p], Bu + bFrag + p * 16 * MM_PADB + 64 + ks * 32);
#pragma unroll
            for (int mt = 0; mt < 4; mt++)
#pragma unroll
                for (int p = 0; p < 4; p++) {
                    mma_bf16(acc[mt][2 * p],     ah[mt], xl[p]);
                    mma_bf16(acc[mt][2 * p + 1], ah[mt], xl[p] + 2);
                }
#pragma unroll
            for (int mt = 0; mt < 4; mt++)
                ldm_x4(xl[mt], Au + aFrag + mt * 16 * MM_PADB + 64 + ks * 32);
#pragma unroll
            for (int mt = 0; mt < 4; mt++)
#pragma unroll
                for (int p = 0; p < 4; p++) {
                    mma_bf16(acc[mt][2 * p],     xl[mt], bh[p]);
                    mma_bf16(acc[mt][2 * p + 1], xl[mt], bh[p] + 2);
                }
        }
        slot++; if (slot >= MM_STAGES) slot = 0;
    }

    const int erow = lane >> 2;
    const int ecol = (lane & 3) * 2;

    if (!fuse) {
        // ---- plain epilogue with bias (proj GEMM -> final output)
#pragma unroll
        for (int mt = 0; mt < 4; mt++) {
            int row = m0 + warp_m * 64 + mt * 16 + erow;
#pragma unroll
            for (int nt = 0; nt < 8; nt++) {
                int col = n0 + warp_n * 64 + nt * 8 + ecol;
                float b0 = bias[col], b1 = bias[col + 1];
                float* c0 = C + (size_t)row * N + col;
                float* c1 = C + (size_t)(row + 8) * N + col;
                c0[0] = acc[mt][nt][0] + b0;
                c0[1] = acc[mt][nt][1] + b1;
                c1[0] = acc[mt][nt][2] + b0;
                c1[1] = acc[mt][nt][3] + b1;
            }
        }
        return;
    }

    // ---- fused epilogue: this 128x128 tile is one head of Q, K or V
    __syncthreads();                         // smem stages free now
    float* st = (float*)mmsm;                // [128][EP_PAD]
#pragma unroll
    for (int mt = 0; mt < 4; mt++) {
        int r0 = warp_m * 64 + mt * 16 + erow;
#pragma unroll
        for (int nt = 0; nt < 8; nt++) {
            int cc = warp_n * 64 + nt * 8 + ecol;
            float b0 = bias[n0 + cc], b1 = bias[n0 + cc + 1];
            st[r0 * EP_PAD + cc]           = acc[mt][nt][0] + b0;
            st[r0 * EP_PAD + cc + 1]       = acc[mt][nt][1] + b1;
            st[(r0 + 8) * EP_PAD + cc]     = acc[mt][nt][2] + b0;
            st[(r0 + 8) * EP_PAD + cc + 1] = acc[mt][nt][3] + b1;
        }
    }
    __syncthreads();

    const int cbi  = n0 >> 7;            // 0..35
    const int kind = cbi / NHEADS;       // 0=Q, 1=K, 2=V
    const int head = cbi % NHEADS;
    const int s    = m0 + tid;           // this thread's sequence row
    const float* row = st + tid * EP_PAD;
    __nv_bfloat16* dst =
        (kind == 0 ? g_q2 : (kind == 1 ? g_k2 : g_v2)) + ((size_t)head * SEQ + s) * (2 * HDIM);

    if (kind == 2) {
        // V: split only
#pragma unroll 4
        for (int c = 0; c < HDIM; c += 2) {
            float v0 = row[c], v1 = row[c + 1];
            float h0 = __bfloat162float(__float2bfloat16(v0));
            float h1 = __bfloat162float(__float2bfloat16(v1));
            *(uint32_t*)(dst + c)        = pack2bf(v0, v1);
            *(uint32_t*)(dst + HDIM + c) = pack2bf(v0 - h0, v1 - h1);
        }
    } else {
        // Q/K: RMSNorm + RoPE + split
        float ss = 0.f;
#pragma unroll 8
        for (int c = 0; c < HDIM; c++) { float v = row[c]; ss += v * v; }
        const float rms = rsqrtf(ss * (1.0f / HDIM) + EPS);
        const float* w = kind ? kw : qw;
#pragma unroll 4
        for (int c = 0; c < HDIM; c += 2) {
            int d2 = (c < D2) ? c : c - D2;
            float xa = row[c]     * rms * w[c];
            float xb = row[c + 1] * rms * w[c + 1];
            float pa = row[c ^ D2]       * rms * w[c ^ D2];
            float pb = row[(c + 1) ^ D2] * rms * w[(c + 1) ^ D2];
            float ca = cosb[s * D2 + d2],     sa = sinb[s * D2 + d2];
            float cb = cosb[s * D2 + d2 + 1], sb = sinb[s * D2 + d2 + 1];
            float oa = (c < D2) ? xa * ca - pa * sa : xa * ca + pa * sa;
            float ob = (c < D2) ? xb * cb - pb * sb : xb * cb + pb * sb;
            float ha = __bfloat162float(__float2bfloat16(oa));
            float hb = __bfloat162float(__float2bfloat16(ob));
            *(uint32_t*)(dst + c)        = pack2bf(oa, ob);
            *(uint32_t*)(dst + HDIM + c) = pack2bf(oa - ha, ob - hb);
        }
    }
}

// ============================================================================
// tensor-core flash attention (R8 BQ=64 config, 128 threads, 4 warps)
// tiles: 64 rows x 528B (256B hi | 256B lo | 16B pad)
// ============================================================================
#define AT_ROWB  528
#define AT_TILEB (64 * AT_ROWB)          // 33792
#define AT_SMEM_B (3 * AT_TILEB)         // 101376

__global__ __launch_bounds__(128) void attn_mma(const int* __restrict__ cu, int ncu)
{
    extern __shared__ char at_smem[];
    const uint32_t S_u = smem_to_u32(at_smem);
    const uint32_t Q_u = S_u;
    const uint32_t K_u = S_u + AT_TILEB;
    const uint32_t V_u = S_u + 2 * AT_TILEB;
    __shared__ int scu[16];

    const int h    = blockIdx.y;
    const int q0   = blockIdx.x * 64;
    const int tid  = threadIdx.x;
    const int warp = tid >> 5;
    const int lane = tid & 31;

    const size_t hb = (size_t)h * SEQ * (2 * HDIM);

    auto issueTile = [&](uint32_t dst, const __nv_bfloat16* src, int kb, int khi) {
#pragma unroll
        for (int c = 0; c < 16; c++) {
            int i = c * 128 + tid;
            int row = i >> 5, ch = (i & 31) * 16;
            int gr = kb + row; if (gr > khi - 1) gr = khi - 1;
            CP_ASYNC16(dst + (uint32_t)(row * AT_ROWB + ch),
                       (const char*)(src + hb + (size_t)gr * (2 * HDIM)) + ch);
        }
    };

    if (tid < ncu && tid < 16) scu[tid] = cu[tid];
    __syncthreads();

    auto seg = [&](int p) {
        int sgi = 0;
        for (int i = 1; i < ncu; i++) sgi += (scu[i] <= p) ? 1 : 0;
        return sgi;
    };
    int klo, khi;
    {
        int s0 = seg(q0), s1 = seg(q0 + 63);
        if (s0 == s1) { klo = scu[s0]; khi = scu[s0 + 1]; }
        else          { klo = 0;       khi = SEQ; }
    }

    // prologue: group0 = Q + K(klo); group1 = V(klo)
    issueTile(Q_u, g_q2, q0, q0 + 64);
    issueTile(K_u, g_k2, klo, khi);
    CP_COMMIT();
    issueTile(V_u, g_v2, klo, khi);
    CP_COMMIT();

    const int rloc  = lane >> 2;
    const int r0g   = q0 + warp * 16 + rloc;
    const int r1g   = r0g + 8;
    const int sq0   = seg(r0g), sq1 = seg(r1g);

    float m0 = -1e30f, m1 = -1e30f, l0 = 0.f, l1 = 0.f;
    float o[16][4];
#pragma unroll
    for (int nt = 0; nt < 16; nt++)
#pragma unroll
        for (int q = 0; q < 4; q++) o[nt][q] = 0.f;

    const uint32_t aoff = (uint32_t)((warp * 16 + (lane & 15)) * AT_ROWB + ((lane >> 4) * 8) * 2);
    const uint32_t boff = (uint32_t)(((lane & 7) + ((lane >> 4) << 3)) * AT_ROWB + (((lane >> 3) & 1) * 8) * 2);
    const uint32_t voff = (uint32_t)((((lane >> 3) & 1) * 8 + (lane & 7)) * AT_ROWB + ((lane >> 4) * 8) * 2);

    // Q resident after first wait; preload all Q fragments (hi+lo) into registers
    CP_WAIT1();
    __syncthreads();
    uint32_t qh[8][4], ql[8][4];
#pragma unroll
    for (int ks = 0; ks < 8; ks++) {
        ldm_x4(qh[ks], Q_u + aoff + ks * 32);
        ldm_x4(ql[ks], Q_u + aoff + 256 + ks * 32);
    }

    for (int kb = klo; kb < khi; kb += 64) {
        const int knext = kb + 64;

        CP_WAIT1();          // K(kb) resident
        __syncthreads();

        // ---- S = scale * (Qh Kh^T + Ql Kh^T + Qh Kl^T)
        float s[8][4];
#pragma unroll
        for (int nt = 0; nt < 8; nt++)
#pragma unroll
            for (int q = 0; q < 4; q++) s[nt][q] = 0.f;

#pragma unroll
        for (int ks = 0; ks < 8; ks++) {
            uint32_t kf[4][4];
#pragma unroll
            for (int np = 0; np < 4; np++)
                ldm_x4(kf[np], K_u + boff + np * 16 * AT_ROWB + ks * 32);
#pragma unroll
            for (int np = 0; np < 4; np++) {
                mma_bf16(s[2 * np],     qh[ks], kf[np]);
                mma_bf16(s[2 * np + 1], qh[ks], kf[np] + 2);
                mma_bf16(s[2 * np],     ql[ks], kf[np]);
                mma_bf16(s[2 * np + 1], ql[ks], kf[np] + 2);
            }
#pragma unroll
            for (int np = 0; np < 4; np++)
                ldm_x4(kf[np], K_u + boff + np * 16 * AT_ROWB + 256 + ks * 32);
#pragma unroll
            for (int np = 0; np < 4; np++) {
                mma_bf16(s[2 * np],     qh[ks], kf[np]);
                mma_bf16(s[2 * np + 1], qh[ks], kf[np] + 2);
            }
        }

        __syncthreads();                       // all warps done reading K
        if (knext < khi) issueTile(K_u, g_k2, knext, khi);
        CP_COMMIT();

        // ---- scale + segment mask
#pragma unroll
        for (int nt = 0; nt < 8; nt++) {
            int j0 = kb + nt * 8 + (lane & 3) * 2;
            int j1 = j0 + 1;
            int sk0 = (j0 < khi) ? seg(j0) : -1;
            int sk1 = (j1 < khi) ? seg(j1) : -1;
            s[nt][0] = (sk0 == sq0) ? s[nt][0] * ATT_SCALE : -1e30f;
            s[nt][1] = (sk1 == sq0) ? s[nt][1] * ATT_SCALE : -1e30f;
            s[nt][2] = (sk0 == sq1) ? s[nt][2] * ATT_SCALE : -1e30f;
            s[nt][3] = (sk1 == sq1) ? s[nt][3] * ATT_SCALE : -1e30f;
        }

        // ---- online softmax
        float mx0 = -1e30f, mx1 = -1e30f;
#pragma unroll
        for (int nt = 0; nt < 8; nt++) {
            mx0 = fmaxf(mx0, fmaxf(s[nt][0], s[nt][1]));
            mx1 = fmaxf(mx1, fmaxf(s[nt][2], s[nt][3]));
        }
        mx0 = fmaxf(mx0, __shfl_xor_sync(0xffffffffu, mx0, 1));
        mx0 = fmaxf(mx0, __shfl_xor_sync(0xffffffffu, mx0, 2));
        mx1 = fmaxf(mx1, __shfl_xor_sync(0xffffffffu, mx1, 1));
        mx1 = fmaxf(mx1, __shfl_xor_sync(0xffffffffu, mx1, 2));
        float mn0 = fmaxf(m0, mx0), mn1 = fmaxf(m1, mx1);
        bool live0 = mn0 > -1e29f, live1 = mn1 > -1e29f;
        float a0 = live0 ? __expf(m0 - mn0) : 1.f;
        float a1 = live1 ? __expf(m1 - mn1) : 1.f;
        float ls0 = 0.f, ls1 = 0.f;
#pragma unroll
        for (int nt = 0; nt < 8; nt++) {
            float p0 = live0 ? __expf(s[nt][0] - mn0) : 0.f;
            float p1 = live0 ? __expf(s[nt][1] - mn0) : 0.f;
            float p2 = live1 ? __expf(s[nt][2] - mn1) : 0.f;
            float p3 = live1 ? __expf(s[nt][3] - mn1) : 0.f;
            s[nt][0] = p0; s[nt][1] = p1; s[nt][2] = p2; s[nt][3] = p3;
            ls0 += p0 + p1; ls1 += p2 + p3;
        }
        ls0 += __shfl_xor_sync(0xffffffffu, ls0, 1);
        ls0 += __shfl_xor_sync(0xffffffffu, ls0, 2);
        ls1 += __shfl_xor_sync(0xffffffffu, ls1, 1);
        ls1 += __shfl_xor_sync(0xffffffffu, ls1, 2);
        l0 = l0 * a0 + ls0;  l1 = l1 * a1 + ls1;
        m0 = mn0;  m1 = mn1;

#pragma unroll
        for (int nt = 0; nt < 16; nt++) {
            o[nt][0] *= a0; o[nt][1] *= a0;
            o[nt][2] *= a1; o[nt][3] *= a1;
        }

        CP_WAIT1();          // V(kb) resident (pending: K(knext))
        __syncthreads();

        // ---- O += Ph Vh + Pl Vh + Ph Vl
#pragma unroll
        for (int js = 0; js < 4; js++) {
            float* t0 = s[2 * js];
            float* t1 = s[2 * js + 1];
            uint32_t ph[4], pl[4];
            ph[0] = pack2bf(t0[0], t0[1]);
            ph[1] = pack2bf(t0[2], t0[3]);
            ph[2] = pack2bf(t1[0], t1[1]);
            ph[3] = pack2bf(t1[2], t1[3]);
            float r00 = t0[0] - __bfloat162float(__float2bfloat16(t0[0]));
            float r01 = t0[1] - __bfloat162float(__float2bfloat16(t0[1]));
            float r02 = t0[2] - __bfloat162float(__float2bfloat16(t0[2]));
            float r03 = t0[3] - __bfloat162float(__float2bfloat16(t0[3]));
            float r10 = t1[0] - __bfloat162float(__float2bfloat16(t1[0]));
            float r11 = t1[1] - __bfloat162float(__float2bfloat16(t1[1]));
            float r12 = t1[2] - __bfloat162float(__float2bfloat16(t1[2]));
            float r13 = t1[3] - __bfloat162float(__float2bfloat16(t1[3]));
            pl[0] = pack2bf(r00, r01);
            pl[1] = pack2bf(r02, r03);
            pl[2] = pack2bf(r10, r11);
            pl[3] = pack2bf(r12, r13);

            uint32_t vbase = (uint32_t)(js * 16 * AT_ROWB) + voff;
#pragma unroll
            for (int dp = 0; dp < 8; dp++) {
                uint32_t vh4[4], vl4[4];
                ldm_x4_trans(vh4, V_u + vbase + dp * 32);
                mma_bf16(o[2 * dp],     ph, vh4);
                mma_bf16(o[2 * dp + 1], ph, vh4 + 2);
                mma_bf16(o[2 * dp],     pl, vh4);
                mma_bf16(o[2 * dp + 1], pl, vh4 + 2);
                ldm_x4_trans(vl4, V_u + vbase + 256 + dp * 32);
                mma_bf16(o[2 * dp],     ph, vl4);
                mma_bf16(o[2 * dp + 1], ph, vl4 + 2);
            }
        }

        __syncthreads();                       // all warps done reading V
        if (knext < khi) issueTile(V_u, g_v2, knext, khi);
        CP_COMMIT();
    }

    // ---- epilogue: write split bf16 (hi | lo) into g_Actx [m][2K]
    float inv0 = 1.0f / fmaxf(l0, 1e-30f);
    float inv1 = 1.0f / fmaxf(l1, 1e-30f);
    const int cb = h * HDIM + (lane & 3) * 2;
    __nv_bfloat16* row0 = g_Actx + (size_t)r0g * K2;
    __nv_bfloat16* row1 = g_Actx + (size_t)r1g * K2;
#pragma unroll
    for (int nt = 0; nt < 16; nt++) {
        int k = cb + nt * 8;
        float v00 = o[nt][0] * inv0, v01 = o[nt][1] * inv0;
        float v10 = o[nt][2] * inv1, v11 = o[nt][3] * inv1;
        float h00 = __bfloat162float(__float2bfloat16(v00));
        float h01 = __bfloat162float(__float2bfloat16(v01));
        float h10 = __bfloat162float(__float2bfloat16(v10));
        float h11 = __bfloat162float(__float2bfloat16(v11));
        *(uint32_t*)(row0 + k)         = pack2bf(v00, v01);
        *(uint32_t*)(row0 + EMBED + k) = pack2bf(v00 - h00, v01 - h01);
        *(uint32_t*)(row1 + k)         = pack2bf(v10, v11);
        *(uint32_t*)(row1 + EMBED + k) = pack2bf(v10 - h10, v11 - h11);
    }
}

// ============================================================================
// launch
// ============================================================================
extern "C" void kernel_launch(void* const* d_in, const int* in_sizes, int n_in,
                              void* d_out, int out_size)
{
    const float* x      = (const float*)d_in[0];
    const int*   cu     = (const int*)  d_in[1];
    const float* cosb   = (const float*)d_in[2];
    const float* sinb   = (const float*)d_in[3];
    const float* w_qkv  = (const float*)d_in[4];
    const float* b_qkv  = (const float*)d_in[5];
    const float* qw     = (const float*)d_in[6];
    const float* kw     = (const float*)d_in[7];
    const float* w_proj = (const float*)d_in[8];
    const float* b_proj = (const float*)d_in[9];
    float* out = (float*)d_out;
    const int ncu = in_sizes[1];

    __nv_bfloat16 *Ax_p, *Actx_p, *Wtqkv_p, *Wtprj_p;
    cudaGetSymbolAddress((void**)&Ax_p,    g_Ax);
    cudaGetSymbolAddress((void**)&Actx_p,  g_Actx);
    cudaGetSymbolAddress((void**)&Wtqkv_p, g_Wtqkv);
    cudaGetSymbolAddress((void**)&Wtprj_p, g_Wtprj);

    cudaFuncSetAttribute(attn_mma, cudaFuncAttributeMaxDynamicSharedMemorySize, AT_SMEM_B);
    cudaFuncSetAttribute(gemm_mma, cudaFuncAttributeMaxDynamicSharedMemorySize, MM_SMEM);

    // split conversions (hi|lo 2K layouts)
    conv_split_A<<<(SEQ * EMBED + 255) / 256, 256>>>(x, Ax_p, SEQ, EMBED);
    conv_split_Wt<<<dim3(EMBED / 32, QKV_N / 32), dim3(32, 8)>>>(w_qkv, Wtqkv_p, EMBED, QKV_N);
    conv_split_Wt<<<dim3(EMBED / 32, EMBED / 32), dim3(32, 8)>>>(w_proj, Wtprj_p, EMBED, EMBED);

    // 1) QKV GEMM with fused RMSNorm + RoPE + hi/lo split epilogue
    gemm_mma<<<dim3(QKV_N / MM_BN, SEQ / MM_BM), 128, MM_SMEM>>>(
        Ax_p, Wtqkv_p, b_qkv, nullptr, QKV_N, EMBED, 1, cosb, sinb, qw, kw);

    // 2) tensor-core flash attention BQ=64 (writes split proj input directly)
    attn_mma<<<dim3(SEQ / 64, NHEADS), 128, AT_SMEM_B>>>(cu, ncu);

    // 3) out = ctx @ w_proj + b_proj
    gemm_mma<<<dim3(EMBED / MM_BN, SEQ / MM_BM), 128, MM_SMEM>>>(
        Actx_p, Wtprj_p, b_proj, out, EMBED, EMBED, 0, nullptr, nullptr, nullptr, nullptr);
}

// round 12
// speedup vs baseline: 1.1473x; 1.1473x over previous
#include <cuda_runtime.h>
#include <cuda_bf16.h>
#include <math.h>
#include <stdint.h>

#define SEQ       2048
#define EMBED     1536
#define NHEADS    12
#define HDIM      128
#define QKV_N     (3 * EMBED)         // 4608
#define K2        (2 * EMBED)         // hi|lo layout width = 3072
#define D2        (HDIM / 2)          // 64
#define EPS       1e-5f
#define ATT_SCALE 0.08838834764831843f   // 1/sqrt(128)

// ---------------- scratch (device globals) ----------------
__device__ __nv_bfloat16 g_Ax   [SEQ * K2];             // x split   [m][hi|lo]
__device__ __nv_bfloat16 g_Actx [SEQ * K2];             // ctx split [m][hi|lo] (written by attn)
__device__ __nv_bfloat16 g_Wtqkv[QKV_N * K2];           // W_qkv^T split  (N x 2K)
__device__ __nv_bfloat16 g_Wtprj[EMBED * K2];           // W_proj^T split (N x 2K)
// attention operands merged hi|lo: [h][s][256] (hi at d, lo at 128+d)
__device__ __nv_bfloat16 g_q2[NHEADS * SEQ * 2 * HDIM];
__device__ __nv_bfloat16 g_k2[NHEADS * SEQ * 2 * HDIM];
__device__ __nv_bfloat16 g_v2[NHEADS * SEQ * 2 * HDIM];

// ============================================================================
// helpers
// ============================================================================
__device__ __forceinline__ uint32_t smem_to_u32(const void* p) {
    uint32_t a;
    asm("{ .reg .u64 t; cvta.to.shared.u64 t, %1; cvt.u32.u64 %0, t; }" : "=r"(a) : "l"(p));
    return a;
}
#define CP_ASYNC16(saddr, gptr) \
    asm volatile("cp.async.cg.shared.global [%0], [%1], 16;" \
        :: "r"(saddr), "l"(gptr) : "memory")
#define CP_COMMIT() asm volatile("cp.async.commit_group;" ::: "memory")
#define CP_WAIT1()  asm volatile("cp.async.wait_group 1;" ::: "memory")

__device__ __forceinline__ void ldm_x4(uint32_t* r, uint32_t addr) {
    asm volatile("ldmatrix.sync.aligned.m8n8.x4.shared.b16 {%0,%1,%2,%3}, [%4];"
        : "=r"(r[0]), "=r"(r[1]), "=r"(r[2]), "=r"(r[3]) : "r"(addr));
}
__device__ __forceinline__ void ldm_x4_trans(uint32_t* r, uint32_t addr) {
    asm volatile("ldmatrix.sync.aligned.m8n8.x4.trans.shared.b16 {%0,%1,%2,%3}, [%4];"
        : "=r"(r[0]), "=r"(r[1]), "=r"(r[2]), "=r"(r[3]) : "r"(addr));
}
__device__ __forceinline__ void mma_bf16(float* d, const uint32_t* a, const uint32_t* b) {
    asm volatile(
        "mma.sync.aligned.m16n8k16.row.col.f32.bf16.bf16.f32 "
        "{%0,%1,%2,%3}, {%4,%5,%6,%7}, {%8,%9}, {%0,%1,%2,%3};"
        : "+f"(d[0]), "+f"(d[1]), "+f"(d[2]), "+f"(d[3])
        : "r"(a[0]), "r"(a[1]), "r"(a[2]), "r"(a[3]), "r"(b[0]), "r"(b[1]));
}
__device__ __forceinline__ uint32_t pack2bf(float lo, float hi) {
    __nv_bfloat162 t = __floats2bfloat162_rn(lo, hi);
    return *(uint32_t*)&t;
}

// ============================================================================
// Split-bf16 conversion kernels (hi|lo 2K layouts)
// ============================================================================
__global__ __launch_bounds__(256) void conv_split_A(
    const float* __restrict__ src, __nv_bfloat16* __restrict__ dst, int M, int K)
{
    int idx = blockIdx.x * 256 + threadIdx.x;
    if (idx >= M * K) return;
    int m = idx / K, k = idx - m * K;
    float x  = src[idx];
    __nv_bfloat16 hi = __float2bfloat16(x);
    __nv_bfloat16 lo = __float2bfloat16(x - __bfloat162float(hi));
    __nv_bfloat16* row = dst + (size_t)m * (2 * K);
    row[k]     = hi;
    row[K + k] = lo;
}

__global__ __launch_bounds__(256) void conv_split_Wt(
    const float* __restrict__ W, __nv_bfloat16* __restrict__ Wt, int K, int N)
{
    __shared__ float tile[32][33];
    int k0 = blockIdx.x * 32, n0 = blockIdx.y * 32;
    int tx = threadIdx.x, ty = threadIdx.y;   // block (32, 8)
#pragma unroll
    for (int r = 0; r < 32; r += 8)
        tile[ty + r][tx] = W[(size_t)(k0 + ty + r) * N + n0 + tx];
    __syncthreads();
#pragma unroll
    for (int r = 0; r < 32; r += 8) {
        int n = n0 + ty + r, k = k0 + tx;
        float x  = tile[tx][ty + r];
        __nv_bfloat16 hi = __float2bfloat16(x);
        __nv_bfloat16 lo = __float2bfloat16(x - __bfloat162float(hi));
        __nv_bfloat16* row = Wt + (size_t)n * (2 * K);
        row[k]     = hi;
        row[K + k] = lo;
    }
}

// ============================================================================
// mma.sync GEMM (shared-operand split): C = A @ Bt^T + bias
// fuse==1 (QKV): epilogue does RMSNorm+RoPE+hi/lo split, writes g_q2/g_k2/g_v2
//                with warp-per-row COALESCED global stores.
// fuse==0 (proj): plain fp32 write with bias.
// ============================================================================
#define MM_BM     128
#define MM_BN     128
#define MM_PADB   144
#define MM_TILEB  (128 * MM_PADB)            // 18432
#define MM_STAGEB (2 * MM_TILEB)             // 36864
#define MM_STAGES 3
#define MM_SMEM   (MM_STAGES * MM_STAGEB)    // 110592
#define EP_PAD    132                        // fp32 epilogue tile row stride (16B-mult)

__device__ __forceinline__ void mm_load_tile(
    const __nv_bfloat16* __restrict__ src, int row0, int kk, int chunk,
    uint32_t dstBase, int tid)
{
#pragma unroll
    for (int c2 = 0; c2 < 8; c2++) {
        int idx = c2 * 128 + tid;
        int row = idx >> 3;
        int c16 = idx & 7;           // 0..3 hi, 4..7 lo
        const char* gb = (const char*)(src + (size_t)(row0 + row) * (2 * kk));
        const char* g  = (c16 < 4)
            ? gb + chunk * 64 + c16 * 16
            : gb + (size_t)kk * 2 + chunk * 64 + (c16 - 4) * 16;
        CP_ASYNC16(dstBase + (uint32_t)(row * MM_PADB + c16 * 16), g);
    }
}

__global__ __launch_bounds__(128, 2) void gemm_mma(
    const __nv_bfloat16* __restrict__ A, const __nv_bfloat16* __restrict__ Bt,
    const float* __restrict__ bias, float* __restrict__ C, int N, int kk,
    int fuse,
    const float* __restrict__ cosb, const float* __restrict__ sinb,
    const float* __restrict__ qw,   const float* __restrict__ kw)
{
    extern __shared__ char mmsm[];
    const uint32_t S_u = smem_to_u32(mmsm);

    const int tid    = threadIdx.x;
    const int lane   = tid & 31;
    const int wid    = tid >> 5;
    const int warp_m = wid & 1;
    const int warp_n = wid >> 1;
    const int m0 = blockIdx.y * MM_BM;
    const int n0 = blockIdx.x * MM_BN;
    const int nchunk = kk / 32;        // 48

    float acc[4][8][4];
#pragma unroll
    for (int mt = 0; mt < 4; mt++)
#pragma unroll
        for (int nt = 0; nt < 8; nt++)
#pragma unroll
            for (int q = 0; q < 4; q++) acc[mt][nt][q] = 0.f;

    const uint32_t aFrag = (uint32_t)((warp_m * 64 + (lane & 15)) * MM_PADB + (lane >> 4) * 16);
    const uint32_t bFrag = (uint32_t)((warp_n * 64 + ((lane >> 4) << 3) + (lane & 7)) * MM_PADB
                                      + ((lane >> 3) & 1) * 16);

    mm_load_tile(A,  m0, kk, 0, S_u,             tid);
    mm_load_tile(Bt, n0, kk, 0, S_u + MM_TILEB,  tid);
    CP_COMMIT();
    mm_load_tile(A,  m0, kk, 1, S_u + MM_STAGEB,            tid);
    mm_load_tile(Bt, n0, kk, 1, S_u + MM_STAGEB + MM_TILEB, tid);
    CP_COMMIT();

    int slot = 0;
    for (int c = 0; c < nchunk; ++c) {
        CP_WAIT1();
        __syncthreads();
        if (c + 2 < nchunk) {
            int ns = slot + 2; if (ns >= MM_STAGES) ns -= MM_STAGES;
            mm_load_tile(A,  m0, kk, c + 2, S_u + ns * MM_STAGEB,            tid);
            mm_load_tile(Bt, n0, kk, c + 2, S_u + ns * MM_STAGEB + MM_TILEB, tid);
        }
        CP_COMMIT();

        const uint32_t Au = S_u + slot * MM_STAGEB;
        const uint32_t Bu = Au + MM_TILEB;
#pragma unroll
        for (int ks = 0; ks < 2; ++ks) {
            uint32_t ah[4][4], bh[4][4], xl[4][4];
#pragma unroll
            for (int mt = 0; mt < 4; mt++)
                ldm_x4(ah[mt], Au + aFrag + mt * 16 * MM_PADB + ks * 32);
#pragma unroll
            for (int p = 0; p < 4; p++)
                ldm_x4(bh[p], Bu + bFrag + p * 16 * MM_PADB + ks * 32);
#pragma unroll
            for (int mt = 0; mt < 4; mt++)
#pragma unroll
                for (int p = 0; p < 4; p++) {
                    mma_bf16(acc[mt][2 * p],     ah[mt], bh[p]);
                    mma_bf16(acc[mt][2 * p + 1], ah[mt], bh[p] + 2);
                }
#pragma unroll
            for (int p = 0; p < 4; p++)
                ldm_x4(xl[p], Bu + bFrag + p * 16 * MM_PADB + 64 + ks * 32);
#pragma unroll
            for (int mt = 0; mt < 4; mt++)
#pragma unroll
                for (int p = 0; p < 4; p++) {
                    mma_bf16(acc[mt][2 * p],     ah[mt], xl[p]);
                    mma_bf16(acc[mt][2 * p + 1], ah[mt], xl[p] + 2);
                }
#pragma unroll
            for (int mt = 0; mt < 4; mt++)
                ldm_x4(xl[mt], Au + aFrag + mt * 16 * MM_PADB + 64 + ks * 32);
#pragma unroll
            for (int mt = 0; mt < 4; mt++)
#pragma unroll
                for (int p = 0; p < 4; p++) {
                    mma_bf16(acc[mt][2 * p],     xl[mt], bh[p]);
                    mma_bf16(acc[mt][2 * p + 1], xl[mt], bh[p] + 2);
                }
        }
        slot++; if (slot >= MM_STAGES) slot = 0;
    }

    const int erow = lane >> 2;
    const int ecol = (lane & 3) * 2;

    if (!fuse) {
        // ---- plain epilogue with bias (proj GEMM -> final output)
#pragma unroll
        for (int mt = 0; mt < 4; mt++) {
            int row = m0 + warp_m * 64 + mt * 16 + erow;
#pragma unroll
            for (int nt = 0; nt < 8; nt++) {
                int col = n0 + warp_n * 64 + nt * 8 + ecol;
                float b0 = bias[col], b1 = bias[col + 1];
                float* c0 = C + (size_t)row * N + col;
                float* c1 = C + (size_t)(row + 8) * N + col;
                c0[0] = acc[mt][nt][0] + b0;
                c0[1] = acc[mt][nt][1] + b1;
                c1[0] = acc[mt][nt][2] + b0;
                c1[1] = acc[mt][nt][3] + b1;
            }
        }
        return;
    }

    // ---- fused epilogue: this 128x128 tile is one head of Q, K or V.
    // Stage to smem, then WARP-PER-ROW processing with coalesced stores.
    __syncthreads();                         // smem stages free now
    float* st = (float*)mmsm;                // [128][EP_PAD]
#pragma unroll
    for (int mt = 0; mt < 4; mt++) {
        int r0 = warp_m * 64 + mt * 16 + erow;
#pragma unroll
        for (int nt = 0; nt < 8; nt++) {
            int cc = warp_n * 64 + nt * 8 + ecol;
            float b0 = bias[n0 + cc], b1 = bias[n0 + cc + 1];
            st[r0 * EP_PAD + cc]           = acc[mt][nt][0] + b0;
            st[r0 * EP_PAD + cc + 1]       = acc[mt][nt][1] + b1;
            st[(r0 + 8) * EP_PAD + cc]     = acc[mt][nt][2] + b0;
            st[(r0 + 8) * EP_PAD + cc + 1] = acc[mt][nt][3] + b1;
        }
    }
    __syncthreads();

    const int cbi  = n0 >> 7;            // 0..35
    const int kind = cbi / NHEADS;       // 0=Q, 1=K, 2=V
    const int head = cbi % NHEADS;
    __nv_bfloat16* gbase =
        (kind == 0 ? g_q2 : (kind == 1 ? g_k2 : g_v2)) + (size_t)head * SEQ * (2 * HDIM);

    const int c0 = lane * 4;             // this lane's 4 columns
    float4 w4 = make_float4(1.f, 1.f, 1.f, 1.f);
    if (kind != 2) w4 = *(const float4*)((kind ? kw : qw) + c0);
    const int d2b = (lane & 15) * 4;     // cos/sin index base (c0 mod 64)
    const bool lowh = lane < 16;

#pragma unroll 4
    for (int it = 0; it < 32; it++) {
        const int r = it * 4 + wid;      // each warp owns one row per iteration
        const int s = m0 + r;
        const float* row = st + r * EP_PAD;
        float4 v = *(const float4*)(row + c0);
        __nv_bfloat16* dst = gbase + (size_t)s * (2 * HDIM) + c0;

        if (kind == 2) {
            float h0 = __bfloat162float(__float2bfloat16(v.x));
            float h1 = __bfloat162float(__float2bfloat16(v.y));
            float h2 = __bfloat162float(__float2bfloat16(v.z));
            float h3 = __bfloat162float(__float2bfloat16(v.w));
            uint2 hiw = make_uint2(pack2bf(v.x, v.y), pack2bf(v.z, v.w));
            uint2 low = make_uint2(pack2bf(v.x - h0, v.y - h1), pack2bf(v.z - h2, v.w - h3));
            *(uint2*)(dst)        = hiw;
            *(uint2*)(dst + HDIM) = low;
        } else {
            float ssum = v.x * v.x + v.y * v.y + v.z * v.z + v.w * v.w;
#pragma unroll
            for (int o = 16; o; o >>= 1) ssum += __shfl_xor_sync(0xffffffffu, ssum, o);
            const float rms = rsqrtf(ssum * (1.0f / HDIM) + EPS);
            float x0 = v.x * rms * w4.x;
            float x1 = v.y * rms * w4.y;
            float x2 = v.z * rms * w4.z;
            float x3 = v.w * rms * w4.w;
            float p0 = __shfl_xor_sync(0xffffffffu, x0, 16);
            float p1 = __shfl_xor_sync(0xffffffffu, x1, 16);
            float p2 = __shfl_xor_sync(0xffffffffu, x2, 16);
            float p3 = __shfl_xor_sync(0xffffffffu, x3, 16);
            float4 c4 = *(const float4*)(cosb + s * D2 + d2b);
            float4 s4 = *(const float4*)(sinb + s * D2 + d2b);
            float o0, o1, o2, o3;
            if (lowh) {
                o0 = x0 * c4.x - p0 * s4.x;
                o1 = x1 * c4.y - p1 * s4.y;
                o2 = x2 * c4.z - p2 * s4.z;
                o3 = x3 * c4.w - p3 * s4.w;
            } else {
                o0 = x0 * c4.x + p0 * s4.x;
                o1 = x1 * c4.y + p1 * s4.y;
                o2 = x2 * c4.z + p2 * s4.z;
                o3 = x3 * c4.w + p3 * s4.w;
            }
            float h0 = __bfloat162float(__float2bfloat16(o0));
            float h1 = __bfloat162float(__float2bfloat16(o1));
            float h2 = __bfloat162float(__float2bfloat16(o2));
            float h3 = __bfloat162float(__float2bfloat16(o3));
            uint2 hiw = make_uint2(pack2bf(o0, o1), pack2bf(o2, o3));
            uint2 low = make_uint2(pack2bf(o0 - h0, o1 - h1), pack2bf(o2 - h2, o3 - h3));
            *(uint2*)(dst)        = hiw;
            *(uint2*)(dst + HDIM) = low;
        }
    }
}

// ============================================================================
// tensor-core flash attention (R8 BQ=64 config, 128 threads, 4 warps)
// tiles: 64 rows x 528B (256B hi | 256B lo | 16B pad)
// ============================================================================
#define AT_ROWB  528
#define AT_TILEB (64 * AT_ROWB)          // 33792
#define AT_SMEM_B (3 * AT_TILEB)         // 101376

__global__ __launch_bounds__(128) void attn_mma(const int* __restrict__ cu, int ncu)
{
    extern __shared__ char at_smem[];
    const uint32_t S_u = smem_to_u32(at_smem);
    const uint32_t Q_u = S_u;
    const uint32_t K_u = S_u + AT_TILEB;
    const uint32_t V_u = S_u + 2 * AT_TILEB;
    __shared__ int scu[16];

    const int h    = blockIdx.y;
    const int q0   = blockIdx.x * 64;
    const int tid  = threadIdx.x;
    const int warp = tid >> 5;
    const int lane = tid & 31;

    const size_t hb = (size_t)h * SEQ * (2 * HDIM);

    auto issueTile = [&](uint32_t dst, const __nv_bfloat16* src, int kb, int khi) {
#pragma unroll
        for (int c = 0; c < 16; c++) {
            int i = c * 128 + tid;
            int row = i >> 5, ch = (i & 31) * 16;
            int gr = kb + row; if (gr > khi - 1) gr = khi - 1;
            CP_ASYNC16(dst + (uint32_t)(row * AT_ROWB + ch),
                       (const char*)(src + hb + (size_t)gr * (2 * HDIM)) + ch);
        }
    };

    if (tid < ncu && tid < 16) scu[tid] = cu[tid];
    __syncthreads();

    auto seg = [&](int p) {
        int sgi = 0;
        for (int i = 1; i < ncu; i++) sgi += (scu[i] <= p) ? 1 : 0;
        return sgi;
    };
    int klo, khi;
    {
        int s0 = seg(q0), s1 = seg(q0 + 63);
        if (s0 == s1) { klo = scu[s0]; khi = scu[s0 + 1]; }
        else          { klo = 0;       khi = SEQ; }
    }

    // prologue: group0 = Q + K(klo); group1 = V(klo)
    issueTile(Q_u, g_q2, q0, q0 + 64);
    issueTile(K_u, g_k2, klo, khi);
    CP_COMMIT();
    issueTile(V_u, g_v2, klo, khi);
    CP_COMMIT();

    const int rloc  = lane >> 2;
    const int r0g   = q0 + warp * 16 + rloc;
    const int r1g   = r0g + 8;
    const int sq0   = seg(r0g), sq1 = seg(r1g);

    float m0 = -1e30f, m1 = -1e30f, l0 = 0.f, l1 = 0.f;
    float o[16][4];
#pragma unroll
    for (int nt = 0; nt < 16; nt++)
#pragma unroll
        for (int q = 0; q < 4; q++) o[nt][q] = 0.f;

    const uint32_t aoff = (uint32_t)((warp * 16 + (lane & 15)) * AT_ROWB + ((lane >> 4) * 8) * 2);
    const uint32_t boff = (uint32_t)(((lane & 7) + ((lane >> 4) << 3)) * AT_ROWB + (((lane >> 3) & 1) * 8) * 2);
    const uint32_t voff = (uint32_t)((((lane >> 3) & 1) * 8 + (lane & 7)) * AT_ROWB + ((lane >> 4) * 8) * 2);

    // Q resident after first wait; preload all Q fragments (hi+lo) into registers
    CP_WAIT1();
    __syncthreads();
    uint32_t qh[8][4], ql[8][4];
#pragma unroll
    for (int ks = 0; ks < 8; ks++) {
        ldm_x4(qh[ks], Q_u + aoff + ks * 32);
        ldm_x4(ql[ks], Q_u + aoff + 256 + ks * 32);
    }

    for (int kb = klo; kb < khi; kb += 64) {
        const int knext = kb + 64;

        CP_WAIT1();          // K(kb) resident
        __syncthreads();

        // ---- S = scale * (Qh Kh^T + Ql Kh^T + Qh Kl^T)
        float s[8][4];
#pragma unroll
        for (int nt = 0; nt < 8; nt++)
#pragma unroll
            for (int q = 0; q < 4; q++) s[nt][q] = 0.f;

#pragma unroll
        for (int ks = 0; ks < 8; ks++) {
            uint32_t kf[4][4];
#pragma unroll
            for (int np = 0; np < 4; np++)
                ldm_x4(kf[np], K_u + boff + np * 16 * AT_ROWB + ks * 32);
#pragma unroll
            for (int np = 0; np < 4; np++) {
                mma_bf16(s[2 * np],     qh[ks], kf[np]);
                mma_bf16(s[2 * np + 1], qh[ks], kf[np] + 2);
                mma_bf16(s[2 * np],     ql[ks], kf[np]);
                mma_bf16(s[2 * np + 1], ql[ks], kf[np] + 2);
            }
#pragma unroll
            for (int np = 0; np < 4; np++)
                ldm_x4(kf[np], K_u + boff + np * 16 * AT_ROWB + 256 + ks * 32);
#pragma unroll
            for (int np = 0; np < 4; np++) {
                mma_bf16(s[2 * np],     qh[ks], kf[np]);
                mma_bf16(s[2 * np + 1], qh[ks], kf[np] + 2);
            }
        }

        __syncthreads();                       // all warps done reading K
        if (knext < khi) issueTile(K_u, g_k2, knext, khi);
        CP_COMMIT();

        // ---- scale + segment mask
#pragma unroll
        for (int nt = 0; nt < 8; nt++) {
            int j0 = kb + nt * 8 + (lane & 3) * 2;
            int j1 = j0 + 1;
            int sk0 = (j0 < khi) ? seg(j0) : -1;
            int sk1 = (j1 < khi) ? seg(j1) : -1;
            s[nt][0] = (sk0 == sq0) ? s[nt][0] * ATT_SCALE : -1e30f;
            s[nt][1] = (sk1 == sq0) ? s[nt][1] * ATT_SCALE : -1e30f;
            s[nt][2] = (sk0 == sq1) ? s[nt][2] * ATT_SCALE : -1e30f;
            s[nt][3] = (sk1 == sq1) ? s[nt][3] * ATT_SCALE : -1e30f;
        }

        // ---- online softmax
        float mx0 = -1e30f, mx1 = -1e30f;
#pragma unroll
        for (int nt = 0; nt < 8; nt++) {
            mx0 = fmaxf(mx0, fmaxf(s[nt][0], s[nt][1]));
            mx1 = fmaxf(mx1, fmaxf(s[nt][2], s[nt][3]));
        }
        mx0 = fmaxf(mx0, __shfl_xor_sync(0xffffffffu, mx0, 1));
        mx0 = fmaxf(mx0, __shfl_xor_sync(0xffffffffu, mx0, 2));
        mx1 = fmaxf(mx1, __shfl_xor_sync(0xffffffffu, mx1, 1));
        mx1 = fmaxf(mx1, __shfl_xor_sync(0xffffffffu, mx1, 2));
        float mn0 = fmaxf(m0, mx0), mn1 = fmaxf(m1, mx1);
        bool live0 = mn0 > -1e29f, live1 = mn1 > -1e29f;
        float a0 = live0 ? __expf(m0 - mn0) : 1.f;
        float a1 = live1 ? __expf(m1 - mn1) : 1.f;
        float ls0 = 0.f, ls1 = 0.f;
#pragma unroll
        for (int nt = 0; nt < 8; nt++) {
            float p0 = live0 ? __expf(s[nt][0] - mn0) : 0.f;
            float p1 = live0 ? __expf(s[nt][1] - mn0) : 0.f;
            float p2 = live1 ? __expf(s[nt][2] - mn1) : 0.f;
            float p3 = live1 ? __expf(s[nt][3] - mn1) : 0.f;
            s[nt][0] = p0; s[nt][1] = p1; s[nt][2] = p2; s[nt][3] = p3;
            ls0 += p0 + p1; ls1 += p2 + p3;
        }
        ls0 += __shfl_xor_sync(0xffffffffu, ls0, 1);
        ls0 += __shfl_xor_sync(0xffffffffu, ls0, 2);
        ls1 += __shfl_xor_sync(0xffffffffu, ls1, 1);
        ls1 += __shfl_xor_sync(0xffffffffu, ls1, 2);
        l0 = l0 * a0 + ls0;  l1 = l1 * a1 + ls1;
        m0 = mn0;  m1 = mn1;

#pragma unroll
        for (int nt = 0; nt < 16; nt++) {
            o[nt][0] *= a0; o[nt][1] *= a0;
            o[nt][2] *= a1; o[nt][3] *= a1;
        }

        CP_WAIT1();          // V(kb) resident (pending: K(knext))
        __syncthreads();

        // ---- O += Ph Vh + Pl Vh + Ph Vl
#pragma unroll
        for (int js = 0; js < 4; js++) {
            float* t0 = s[2 * js];
            float* t1 = s[2 * js + 1];
            uint32_t ph[4], pl[4];
            ph[0] = pack2bf(t0[0], t0[1]);
            ph[1] = pack2bf(t0[2], t0[3]);
            ph[2] = pack2bf(t1[0], t1[1]);
            ph[3] = pack2bf(t1[2], t1[3]);
            float r00 = t0[0] - __bfloat162float(__float2bfloat16(t0[0]));
            float r01 = t0[1] - __bfloat162float(__float2bfloat16(t0[1]));
            float r02 = t0[2] - __bfloat162float(__float2bfloat16(t0[2]));
            float r03 = t0[3] - __bfloat162float(__float2bfloat16(t0[3]));
            float r10 = t1[0] - __bfloat162float(__float2bfloat16(t1[0]));
            float r11 = t1[1] - __bfloat162float(__float2bfloat16(t1[1]));
            float r12 = t1[2] - __bfloat162float(__float2bfloat16(t1[2]));
            float r13 = t1[3] - __bfloat162float(__float2bfloat16(t1[3]));
            pl[0] = pack2bf(r00, r01);
            pl[1] = pack2bf(r02, r03);
            pl[2] = pack2bf(r10, r11);
            pl[3] = pack2bf(r12, r13);

            uint32_t vbase = (uint32_t)(js * 16 * AT_ROWB) + voff;
#pragma unroll
            for (int dp = 0; dp < 8; dp++) {
                uint32_t vh4[4], vl4[4];
                ldm_x4_trans(vh4, V_u + vbase + dp * 32);
                mma_bf16(o[2 * dp],     ph, vh4);
                mma_bf16(o[2 * dp + 1], ph, vh4 + 2);
                mma_bf16(o[2 * dp],     pl, vh4);
                mma_bf16(o[2 * dp + 1], pl, vh4 + 2);
                ldm_x4_trans(vl4, V_u + vbase + 256 + dp * 32);
                mma_bf16(o[2 * dp],     ph, vl4);
                mma_bf16(o[2 * dp + 1], ph, vl4 + 2);
            }
        }

        __syncthreads();                       // all warps done reading V
        if (knext < khi) issueTile(V_u, g_v2, knext, khi);
        CP_COMMIT();
    }

    // ---- epilogue: write split bf16 (hi | lo) into g_Actx [m][2K]
    float inv0 = 1.0f / fmaxf(l0, 1e-30f);
    float inv1 = 1.0f / fmaxf(l1, 1e-30f);
    const int cb = h * HDIM + (lane & 3) * 2;
    __nv_bfloat16* row0 = g_Actx + (size_t)r0g * K2;
    __nv_bfloat16* row1 = g_Actx + (size_t)r1g * K2;
#pragma unroll
    for (int nt = 0; nt < 16; nt++) {
        int k = cb + nt * 8;
        float v00 = o[nt][0] * inv0, v01 = o[nt][1] * inv0;
        float v10 = o[nt][2] * inv1, v11 = o[nt][3] * inv1;
        float h00 = __bfloat162float(__float2bfloat16(v00));
        float h01 = __bfloat162float(__float2bfloat16(v01));
        float h10 = __bfloat162float(__float2bfloat16(v10));
        float h11 = __bfloat162float(__float2bfloat16(v11));
        *(uint32_t*)(row0 + k)         = pack2bf(v00, v01);
        *(uint32_t*)(row0 + EMBED + k) = pack2bf(v00 - h00, v01 - h01);
        *(uint32_t*)(row1 + k)         = pack2bf(v10, v11);
        *(uint32_t*)(row1 + EMBED + k) = pack2bf(v10 - h10, v11 - h11);
    }
}

// ============================================================================
// launch
// ============================================================================
extern "C" void kernel_launch(void* const* d_in, const int* in_sizes, int n_in,
                              void* d_out, int out_size)
{
    const float* x      = (const float*)d_in[0];
    const int*   cu     = (const int*)  d_in[1];
    const float* cosb   = (const float*)d_in[2];
    const float* sinb   = (const float*)d_in[3];
    const float* w_qkv  = (const float*)d_in[4];
    const float* b_qkv  = (const float*)d_in[5];
    const float* qw     = (const float*)d_in[6];
    const float* kw     = (const float*)d_in[7];
    const float* w_proj = (const float*)d_in[8];
    const float* b_proj = (const float*)d_in[9];
    float* out = (float*)d_out;
    const int ncu = in_sizes[1];

    __nv_bfloat16 *Ax_p, *Actx_p, *Wtqkv_p, *Wtprj_p;
    cudaGetSymbolAddress((void**)&Ax_p,    g_Ax);
    cudaGetSymbolAddress((void**)&Actx_p,  g_Actx);
    cudaGetSymbolAddress((void**)&Wtqkv_p, g_Wtqkv);
    cudaGetSymbolAddress((void**)&Wtprj_p, g_Wtprj);

    cudaFuncSetAttribute(attn_mma, cudaFuncAttributeMaxDynamicSharedMemorySize, AT_SMEM_B);
    cudaFuncSetAttribute(gemm_mma, cudaFuncAttributeMaxDynamicSharedMemorySize, MM_SMEM);

    // split conversions (hi|lo 2K layouts)
    conv_split_A<<<(SEQ * EMBED + 255) / 256, 256>>>(x, Ax_p, SEQ, EMBED);
    conv_split_Wt<<<dim3(EMBED / 32, QKV_N / 32), dim3(32, 8)>>>(w_qkv, Wtqkv_p, EMBED, QKV_N);
    conv_split_Wt<<<dim3(EMBED / 32, EMBED / 32), dim3(32, 8)>>>(w_proj, Wtprj_p, EMBED, EMBED);

    // 1) QKV GEMM with fused RMSNorm + RoPE + hi/lo split epilogue (coalesced)
    gemm_mma<<<dim3(QKV_N / MM_BN, SEQ / MM_BM), 128, MM_SMEM>>>(
        Ax_p, Wtqkv_p, b_qkv, nullptr, QKV_N, EMBED, 1, cosb, sinb, qw, kw);

    // 2) tensor-core flash attention BQ=64 (writes split proj input directly)
    attn_mma<<<dim3(SEQ / 64, NHEADS), 128, AT_SMEM_B>>>(cu, ncu);

    // 3) out = ctx @ w_proj + b_proj
    gemm_mma<<<dim3(EMBED / MM_BN, SEQ / MM_BM), 128, MM_SMEM>>>(
        Actx_p, Wtprj_p, b_proj, out, EMBED, EMBED, 0, nullptr, nullptr, nullptr, nullptr);
}

// round 13
// speedup vs baseline: 1.4305x; 1.2469x over previous
#include <cuda_runtime.h>
#include <cuda_bf16.h>
#include <math.h>
#include <stdint.h>

#define SEQ       2048
#define EMBED     1536
#define NHEADS    12
#define HDIM      128
#define QKV_N     (3 * EMBED)         // 4608
#define K2        (2 * EMBED)         // hi|lo layout width = 3072
#define D2        (HDIM / 2)          // 64
#define EPS       1e-5f
// 1/sqrt(128) * log2(e)  (scores kept in log2 domain; exp2 in softmax)
#define ATT_SCL2  0.12751879524622723f

// ---------------- scratch (device globals) ----------------
__device__ float g_qkv[SEQ * QKV_N];                    // [s][3E] fp32
__device__ __nv_bfloat16 g_Ax   [SEQ * K2];             // x split   [m][hi|lo]
__device__ __nv_bfloat16 g_Actx [SEQ * K2];             // ctx split [m][hi|lo] (written by attn)
__device__ __nv_bfloat16 g_Wtqkv[QKV_N * K2];           // W_qkv^T split  (N x 2K)
__device__ __nv_bfloat16 g_Wtprj[EMBED * K2];           // W_proj^T split (N x 2K)
// attention operands merged hi|lo: [h][s][256] (hi at d, lo at 128+d)
__device__ __nv_bfloat16 g_q2[NHEADS * SEQ * 2 * HDIM];
__device__ __nv_bfloat16 g_k2[NHEADS * SEQ * 2 * HDIM];
__device__ __nv_bfloat16 g_v2[NHEADS * SEQ * 2 * HDIM];

// ============================================================================
// helpers
// ============================================================================
__device__ __forceinline__ uint32_t smem_to_u32(const void* p) {
    uint32_t a;
    asm("{ .reg .u64 t; cvta.to.shared.u64 t, %1; cvt.u32.u64 %0, t; }" : "=r"(a) : "l"(p));
    return a;
}
#define CP_ASYNC16(saddr, gptr) \
    asm volatile("cp.async.cg.shared.global [%0], [%1], 16;" \
        :: "r"(saddr), "l"(gptr) : "memory")
#define CP_COMMIT() asm volatile("cp.async.commit_group;" ::: "memory")
#define CP_WAIT1()  asm volatile("cp.async.wait_group 1;" ::: "memory")

__device__ __forceinline__ void ldm_x4(uint32_t* r, uint32_t addr) {
    asm volatile("ldmatrix.sync.aligned.m8n8.x4.shared.b16 {%0,%1,%2,%3}, [%4];"
        : "=r"(r[0]), "=r"(r[1]), "=r"(r[2]), "=r"(r[3]) : "r"(addr));
}
__device__ __forceinline__ void ldm_x4_trans(uint32_t* r, uint32_t addr) {
    asm volatile("ldmatrix.sync.aligned.m8n8.x4.trans.shared.b16 {%0,%1,%2,%3}, [%4];"
        : "=r"(r[0]), "=r"(r[1]), "=r"(r[2]), "=r"(r[3]) : "r"(addr));
}
__device__ __forceinline__ void mma_bf16(float* d, const uint32_t* a, const uint32_t* b) {
    asm volatile(
        "mma.sync.aligned.m16n8k16.row.col.f32.bf16.bf16.f32 "
        "{%0,%1,%2,%3}, {%4,%5,%6,%7}, {%8,%9}, {%0,%1,%2,%3};"
        : "+f"(d[0]), "+f"(d[1]), "+f"(d[2]), "+f"(d[3])
        : "r"(a[0]), "r"(a[1]), "r"(a[2]), "r"(a[3]), "r"(b[0]), "r"(b[1]));
}
__device__ __forceinline__ uint32_t pack2bf(float lo, float hi) {
    __nv_bfloat162 t = __floats2bfloat162_rn(lo, hi);
    return *(uint32_t*)&t;
}

// ============================================================================
// Split-bf16 conversion kernels (hi|lo 2K layouts)
// ============================================================================
__global__ __launch_bounds__(256) void conv_split_A(
    const float* __restrict__ src, __nv_bfloat16* __restrict__ dst, int M, int K)
{
    int idx = (blockIdx.x * 256 + threadIdx.x) * 4;
    if (idx >= M * K) return;
    int m = idx / K, k = idx - m * K;
    float4 x = *(const float4*)(src + idx);
    float h0 = __bfloat162float(__float2bfloat16(x.x));
    float h1 = __bfloat162float(__float2bfloat16(x.y));
    float h2 = __bfloat162float(__float2bfloat16(x.z));
    float h3 = __bfloat162float(__float2bfloat16(x.w));
    __nv_bfloat16* row = dst + (size_t)m * (2 * K);
    *(uint2*)(row + k)     = make_uint2(pack2bf(x.x, x.y), pack2bf(x.z, x.w));
    *(uint2*)(row + K + k) = make_uint2(pack2bf(x.x - h0, x.y - h1), pack2bf(x.z - h2, x.w - h3));
}

__global__ __launch_bounds__(256) void conv_split_Wt(
    const float* __restrict__ W, __nv_bfloat16* __restrict__ Wt, int K, int N)
{
    __shared__ float tile[32][33];
    int k0 = blockIdx.x * 32, n0 = blockIdx.y * 32;
    int tx = threadIdx.x, ty = threadIdx.y;   // block (32, 8)
#pragma unroll
    for (int r = 0; r < 32; r += 8)
        tile[ty + r][tx] = W[(size_t)(k0 + ty + r) * N + n0 + tx];
    __syncthreads();
#pragma unroll
    for (int r = 0; r < 32; r += 8) {
        int n = n0 + ty + r, k = k0 + tx;
        float x  = tile[tx][ty + r];
        __nv_bfloat16 hi = __float2bfloat16(x);
        __nv_bfloat16 lo = __float2bfloat16(x - __bfloat162float(hi));
        __nv_bfloat16* row = Wt + (size_t)n * (2 * K);
        row[k]     = hi;
        row[K + k] = lo;
    }
}

// ============================================================================
// mma.sync GEMM v5 (shared-operand split): C = A @ Bt^T + bias  (R8 config)
// ============================================================================
#define MM_BM     128
#define MM_BN     128
#define MM_PADB   144
#define MM_TILEB  (128 * MM_PADB)            // 18432
#define MM_STAGEB (2 * MM_TILEB)             // 36864
#define MM_STAGES 3
#define MM_SMEM   (MM_STAGES * MM_STAGEB)    // 110592

__device__ __forceinline__ void mm_load_tile(
    const __nv_bfloat16* __restrict__ src, int row0, int kk, int chunk,
    uint32_t dstBase, int tid)
{
#pragma unroll
    for (int c2 = 0; c2 < 8; c2++) {
        int idx = c2 * 128 + tid;
        int row = idx >> 3;
        int c16 = idx & 7;           // 0..3 hi, 4..7 lo
        const char* gb = (const char*)(src + (size_t)(row0 + row) * (2 * kk));
        const char* g  = (c16 < 4)
            ? gb + chunk * 64 + c16 * 16
            : gb + (size_t)kk * 2 + chunk * 64 + (c16 - 4) * 16;
        CP_ASYNC16(dstBase + (uint32_t)(row * MM_PADB + c16 * 16), g);
    }
}

__global__ __launch_bounds__(128, 2) void gemm_mma(
    const __nv_bfloat16* __restrict__ A, const __nv_bfloat16* __restrict__ Bt,
    const float* __restrict__ bias, float* __restrict__ C, int N, int kk)
{
    extern __shared__ char mmsm[];
    const uint32_t S_u = smem_to_u32(mmsm);

    const int tid    = threadIdx.x;
    const int lane   = tid & 31;
    const int wid    = tid >> 5;
    const int warp_m = wid & 1;
    const int warp_n = wid >> 1;
    const int m0 = blockIdx.y * MM_BM;
    const int n0 = blockIdx.x * MM_BN;
    const int nchunk = kk / 32;        // 48

    float acc[4][8][4];
#pragma unroll
    for (int mt = 0; mt < 4; mt++)
#pragma unroll
        for (int nt = 0; nt < 8; nt++)
#pragma unroll
            for (int q = 0; q < 4; q++) acc[mt][nt][q] = 0.f;

    const uint32_t aFrag = (uint32_t)((warp_m * 64 + (lane & 15)) * MM_PADB + (lane >> 4) * 16);
    const uint32_t bFrag = (uint32_t)((warp_n * 64 + ((lane >> 4) << 3) + (lane & 7)) * MM_PADB
                                      + ((lane >> 3) & 1) * 16);

    mm_load_tile(A,  m0, kk, 0, S_u,             tid);
    mm_load_tile(Bt, n0, kk, 0, S_u + MM_TILEB,  tid);
    CP_COMMIT();
    mm_load_tile(A,  m0, kk, 1, S_u + MM_STAGEB,            tid);
    mm_load_tile(Bt, n0, kk, 1, S_u + MM_STAGEB + MM_TILEB, tid);
    CP_COMMIT();

    int slot = 0;
    for (int c = 0; c < nchunk; ++c) {
        CP_WAIT1();
        __syncthreads();
        if (c + 2 < nchunk) {
            int ns = slot + 2; if (ns >= MM_STAGES) ns -= MM_STAGES;
            mm_load_tile(A,  m0, kk, c + 2, S_u + ns * MM_STAGEB,            tid);
            mm_load_tile(Bt, n0, kk, c + 2, S_u + ns * MM_STAGEB + MM_TILEB, tid);
        }
        CP_COMMIT();

        const uint32_t Au = S_u + slot * MM_STAGEB;
        const uint32_t Bu = Au + MM_TILEB;
#pragma unroll
        for (int ks = 0; ks < 2; ++ks) {
            uint32_t ah[4][4], bh[4][4], xl[4][4];
#pragma unroll
            for (int mt = 0; mt < 4; mt++)
                ldm_x4(ah[mt], Au + aFrag + mt * 16 * MM_PADB + ks * 32);
#pragma unroll
            for (int p = 0; p < 4; p++)
                ldm_x4(bh[p], Bu + bFrag + p * 16 * MM_PADB + ks * 32);
#pragma unroll
            for (int mt = 0; mt < 4; mt++)
#pragma unroll
                for (int p = 0; p < 4; p++) {
                    mma_bf16(acc[mt][2 * p],     ah[mt], bh[p]);
                    mma_bf16(acc[mt][2 * p + 1], ah[mt], bh[p] + 2);
                }
#pragma unroll
            for (int p = 0; p < 4; p++)
                ldm_x4(xl[p], Bu + bFrag + p * 16 * MM_PADB + 64 + ks * 32);
#pragma unroll
            for (int mt = 0; mt < 4; mt++)
#pragma unroll
                for (int p = 0; p < 4; p++) {
                    mma_bf16(acc[mt][2 * p],     ah[mt], xl[p]);
                    mma_bf16(acc[mt][2 * p + 1], ah[mt], xl[p] + 2);
                }
#pragma unroll
            for (int mt = 0; mt < 4; mt++)
                ldm_x4(xl[mt], Au + aFrag + mt * 16 * MM_PADB + 64 + ks * 32);
#pragma unroll
            for (int mt = 0; mt < 4; mt++)
#pragma unroll
                for (int p = 0; p < 4; p++) {
                    mma_bf16(acc[mt][2 * p],     xl[mt], bh[p]);
                    mma_bf16(acc[mt][2 * p + 1], xl[mt], bh[p] + 2);
                }
        }
        slot++; if (slot >= MM_STAGES) slot = 0;
    }

    const int erow = lane >> 2;
    const int ecol = (lane & 3) * 2;
#pragma unroll
    for (int mt = 0; mt < 4; mt++) {
        int row = m0 + warp_m * 64 + mt * 16 + erow;
#pragma unroll
        for (int nt = 0; nt < 8; nt++) {
            int col = n0 + warp_n * 64 + nt * 8 + ecol;
            float b0 = bias[col], b1 = bias[col + 1];
            float* c0 = C + (size_t)row * N + col;
            float* c1 = C + (size_t)(row + 8) * N + col;
            c0[0] = acc[mt][nt][0] + b0;
            c0[1] = acc[mt][nt][1] + b1;
            c1[0] = acc[mt][nt][2] + b0;
            c1[1] = acc[mt][nt][3] + b1;
        }
    }
}

// ============================================================================
// RMSNorm + RoPE + hi/lo split into merged [h][s][256] layout  (R8 version)
// ============================================================================
__global__ __launch_bounds__(128) void norm_rope_split(
    const float* __restrict__ cosb, const float* __restrict__ sinb,
    const float* __restrict__ qw,   const float* __restrict__ kw)
{
    const int s = blockIdx.x, h = blockIdx.y, d = threadIdx.x;
    __shared__ float sh[128];
    __shared__ float wsum[4];
    __shared__ float rms_sh;

    const float* base = g_qkv + (size_t)s * QKV_N + h * HDIM;
    const int d2 = (d < D2) ? d : d - D2;
    const float c  = cosb[s * D2 + d2];
    const float sn = sinb[s * D2 + d2];
    const size_t o2 = ((size_t)h * SEQ + s) * (2 * HDIM) + d;

#pragma unroll
    for (int which = 0; which < 2; which++) {
        const float x = base[which * EMBED + d];
        float v = x * x;
#pragma unroll
        for (int o = 16; o; o >>= 1) v += __shfl_xor_sync(0xffffffffu, v, o);
        if ((d & 31) == 0) wsum[d >> 5] = v;
        __syncthreads();
        if (d == 0)
            rms_sh = rsqrtf((wsum[0] + wsum[1] + wsum[2] + wsum[3]) * (1.0f / HDIM) + EPS);
        __syncthreads();
        const float* w = which ? kw : qw;
        sh[d] = x * rms_sh * w[d];
        __syncthreads();
        float out;
        if (d < D2) out = sh[d] * c - sh[d + D2] * sn;
        else        out = sh[d] * c + sh[d - D2] * sn;
        __nv_bfloat16 hi = __float2bfloat16(out);
        __nv_bfloat16 lo = __float2bfloat16(out - __bfloat162float(hi));
        if (which == 0) { g_q2[o2] = hi; g_q2[o2 + HDIM] = lo; }
        else            { g_k2[o2] = hi; g_k2[o2 + HDIM] = lo; }
        __syncthreads();
    }
    float v = base[2 * EMBED + d];
    __nv_bfloat16 vh = __float2bfloat16(v);
    g_v2[o2]        = vh;
    g_v2[o2 + HDIM] = __float2bfloat16(v - __bfloat162float(vh));
}

// ============================================================================
// tensor-core flash attention (R8 BQ=64 config) + uniform fast path + exp2
// tiles: 64 rows x 528B (256B hi | 256B lo | 16B pad)
// ============================================================================
#define AT_ROWB  528
#define AT_TILEB (64 * AT_ROWB)          // 33792
#define AT_SMEM_B (3 * AT_TILEB)         // 101376

__global__ __launch_bounds__(128) void attn_mma(const int* __restrict__ cu, int ncu)
{
    extern __shared__ char at_smem[];
    const uint32_t S_u = smem_to_u32(at_smem);
    const uint32_t Q_u = S_u;
    const uint32_t K_u = S_u + AT_TILEB;
    const uint32_t V_u = S_u + 2 * AT_TILEB;
    __shared__ int scu[16];

    const int h    = blockIdx.y;
    const int q0   = blockIdx.x * 64;
    const int tid  = threadIdx.x;
    const int warp = tid >> 5;
    const int lane = tid & 31;

    const size_t hb = (size_t)h * SEQ * (2 * HDIM);

    auto issueTile = [&](uint32_t dst, const __nv_bfloat16* src, int kb, int khi) {
#pragma unroll
        for (int c = 0; c < 16; c++) {
            int i = c * 128 + tid;
            int row = i >> 5, ch = (i & 31) * 16;
            int gr = kb + row; if (gr > khi - 1) gr = khi - 1;
            CP_ASYNC16(dst + (uint32_t)(row * AT_ROWB + ch),
                       (const char*)(src + hb + (size_t)gr * (2 * HDIM)) + ch);
        }
    };

    if (tid < ncu && tid < 16) scu[tid] = cu[tid];
    __syncthreads();

    auto seg = [&](int p) {
        int sgi = 0;
        for (int i = 1; i < ncu; i++) sgi += (scu[i] <= p) ? 1 : 0;
        return sgi;
    };
    int klo, khi;
    bool qUniform;
    {
        int s0 = seg(q0), s1 = seg(q0 + 63);
        qUniform = (s0 == s1);
        if (qUniform) { klo = scu[s0]; khi = scu[s0 + 1]; }
        else          { klo = 0;       khi = SEQ; }
    }

    // prologue: group0 = Q + K(klo); group1 = V(klo)
    issueTile(Q_u, g_q2, q0, q0 + 64);
    issueTile(K_u, g_k2, klo, khi);
    CP_COMMIT();
    issueTile(V_u, g_v2, klo, khi);
    CP_COMMIT();

    const int rloc  = lane >> 2;
    const int r0g   = q0 + warp * 16 + rloc;
    const int r1g   = r0g + 8;
    const int sq0   = seg(r0g), sq1 = seg(r1g);

    float m0 = -1e30f, m1 = -1e30f, l0 = 0.f, l1 = 0.f;
    float o[16][4];
#pragma unroll
    for (int nt = 0; nt < 16; nt++)
#pragma unroll
        for (int q = 0; q < 4; q++) o[nt][q] = 0.f;

    const uint32_t aoff = (uint32_t)((warp * 16 + (lane & 15)) * AT_ROWB + ((lane >> 4) * 8) * 2);
    const uint32_t boff = (uint32_t)(((lane & 7) + ((lane >> 4) << 3)) * AT_ROWB + (((lane >> 3) & 1) * 8) * 2);
    const uint32_t voff = (uint32_t)((((lane >> 3) & 1) * 8 + (lane & 7)) * AT_ROWB + ((lane >> 4) * 8) * 2);

    // Q resident after first wait; preload all Q fragments (hi+lo) into registers
    CP_WAIT1();
    __syncthreads();
    uint32_t qh[8][4], ql[8][4];
#pragma unroll
    for (int ks = 0; ks < 8; ks++) {
        ldm_x4(qh[ks], Q_u + aoff + ks * 32);
        ldm_x4(ql[ks], Q_u + aoff + 256 + ks * 32);
    }

    for (int kb = klo; kb < khi; kb += 64) {
        const int knext = kb + 64;
        const bool full = qUniform && (knext <= khi);   // no masking needed

        CP_WAIT1();          // K(kb) resident
        __syncthreads();

        // ---- S = scl2 * (Qh Kh^T + Ql Kh^T + Qh Kl^T)   (log2 domain)
        float s[8][4];
#pragma unroll
        for (int nt = 0; nt < 8; nt++)
#pragma unroll
            for (int q = 0; q < 4; q++) s[nt][q] = 0.f;

#pragma unroll
        for (int ks = 0; ks < 8; ks++) {
            uint32_t kf[4][4];
#pragma unroll
            for (int np = 0; np < 4; np++)
                ldm_x4(kf[np], K_u + boff + np * 16 * AT_ROWB + ks * 32);
#pragma unroll
            for (int np = 0; np < 4; np++) {
                mma_bf16(s[2 * np],     qh[ks], kf[np]);
                mma_bf16(s[2 * np + 1], qh[ks], kf[np] + 2);
                mma_bf16(s[2 * np],     ql[ks], kf[np]);
                mma_bf16(s[2 * np + 1], ql[ks], kf[np] + 2);
            }
#pragma unroll
            for (int np = 0; np < 4; np++)
                ldm_x4(kf[np], K_u + boff + np * 16 * AT_ROWB + 256 + ks * 32);
#pragma unroll
            for (int np = 0; np < 4; np++) {
                mma_bf16(s[2 * np],     qh[ks], kf[np]);
                mma_bf16(s[2 * np + 1], qh[ks], kf[np] + 2);
            }
        }

        __syncthreads();                       // all warps done reading K
        if (knext < khi) issueTile(K_u, g_k2, knext, khi);
        CP_COMMIT();

        // ---- scale (+ segment mask only when needed)
        if (full) {
#pragma unroll
            for (int nt = 0; nt < 8; nt++) {
                s[nt][0] *= ATT_SCL2; s[nt][1] *= ATT_SCL2;
                s[nt][2] *= ATT_SCL2; s[nt][3] *= ATT_SCL2;
            }
        } else {
#pragma unroll
            for (int nt = 0; nt < 8; nt++) {
                int j0 = kb + nt * 8 + (lane & 3) * 2;
                int j1 = j0 + 1;
                int sk0 = (j0 < khi) ? seg(j0) : -1;
                int sk1 = (j1 < khi) ? seg(j1) : -1;
                s[nt][0] = (sk0 == sq0) ? s[nt][0] * ATT_SCL2 : -1e30f;
                s[nt][1] = (sk1 == sq0) ? s[nt][1] * ATT_SCL2 : -1e30f;
                s[nt][2] = (sk0 == sq1) ? s[nt][2] * ATT_SCL2 : -1e30f;
                s[nt][3] = (sk1 == sq1) ? s[nt][3] * ATT_SCL2 : -1e30f;
            }
        }

        // ---- online softmax (exp2; branch-free in the full path)
        float mx0 = -1e30f, mx1 = -1e30f;
#pragma unroll
        for (int nt = 0; nt < 8; nt++) {
            mx0 = fmaxf(mx0, fmaxf(s[nt][0], s[nt][1]));
            mx1 = fmaxf(mx1, fmaxf(s[nt][2], s[nt][3]));
        }
        mx0 = fmaxf(mx0, __shfl_xor_sync(0xffffffffu, mx0, 1));
        mx0 = fmaxf(mx0, __shfl_xor_sync(0xffffffffu, mx0, 2));
        mx1 = fmaxf(mx1, __shfl_xor_sync(0xffffffffu, mx1, 1));
        mx1 = fmaxf(mx1, __shfl_xor_sync(0xffffffffu, mx1, 2));
        float mn0 = fmaxf(m0, mx0), mn1 = fmaxf(m1, mx1);
        float a0, a1, ls0 = 0.f, ls1 = 0.f;
        if (full) {
            a0 = exp2f(m0 - mn0);              // m0=-1e30 first iter -> 0, correct
            a1 = exp2f(m1 - mn1);
#pragma unroll
            for (int nt = 0; nt < 8; nt++) {
                float p0 = exp2f(s[nt][0] - mn0);
                float p1 = exp2f(s[nt][1] - mn0);
                float p2 = exp2f(s[nt][2] - mn1);
                float p3 = exp2f(s[nt][3] - mn1);
                s[nt][0] = p0; s[nt][1] = p1; s[nt][2] = p2; s[nt][3] = p3;
                ls0 += p0 + p1; ls1 += p2 + p3;
            }
        } else {
            bool live0 = mn0 > -1e29f, live1 = mn1 > -1e29f;
            a0 = live0 ? exp2f(m0 - mn0) : 1.f;
            a1 = live1 ? exp2f(m1 - mn1) : 1.f;
#pragma unroll
            for (int nt = 0; nt < 8; nt++) {
                float p0 = live0 ? exp2f(s[nt][0] - mn0) : 0.f;
                float p1 = live0 ? exp2f(s[nt][1] - mn0) : 0.f;
                float p2 = live1 ? exp2f(s[nt][2] - mn1) : 0.f;
                float p3 = live1 ? exp2f(s[nt][3] - mn1) : 0.f;
                s[nt][0] = p0; s[nt][1] = p1; s[nt][2] = p2; s[nt][3] = p3;
                ls0 += p0 + p1; ls1 += p2 + p3;
            }
        }
        ls0 += __shfl_xor_sync(0xffffffffu, ls0, 1);
        ls0 += __shfl_xor_sync(0xffffffffu, ls0, 2);
        ls1 += __shfl_xor_sync(0xffffffffu, ls1, 1);
        ls1 += __shfl_xor_sync(0xffffffffu, ls1, 2);
        l0 = l0 * a0 + ls0;  l1 = l1 * a1 + ls1;
        m0 = mn0;  m1 = mn1;

#pragma unroll
        for (int nt = 0; nt < 16; nt++) {
            o[nt][0] *= a0; o[nt][1] *= a0;
            o[nt][2] *= a1; o[nt][3] *= a1;
        }

        CP_WAIT1();          // V(kb) resident (pending: K(knext))
        __syncthreads();

        // ---- O += Ph Vh + Pl Vh + Ph Vl
#pragma unroll
        for (int js = 0; js < 4; js++) {
            float* t0 = s[2 * js];
            float* t1 = s[2 * js + 1];
            uint32_t ph[4], pl[4];
            ph[0] = pack2bf(t0[0], t0[1]);
            ph[1] = pack2bf(t0[2], t0[3]);
            ph[2] = pack2bf(t1[0], t1[1]);
            ph[3] = pack2bf(t1[2], t1[3]);
            float r00 = t0[0] - __bfloat162float(__float2bfloat16(t0[0]));
            float r01 = t0[1] - __bfloat162float(__float2bfloat16(t0[1]));
            float r02 = t0[2] - __bfloat162float(__float2bfloat16(t0[2]));
            float r03 = t0[3] - __bfloat162float(__float2bfloat16(t0[3]));
            float r10 = t1[0] - __bfloat162float(__float2bfloat16(t1[0]));
            float r11 = t1[1] - __bfloat162float(__float2bfloat16(t1[1]));
            float r12 = t1[2] - __bfloat162float(__float2bfloat16(t1[2]));
            float r13 = t1[3] - __bfloat162float(__float2bfloat16(t1[3]));
            pl[0] = pack2bf(r00, r01);
            pl[1] = pack2bf(r02, r03);
            pl[2] = pack2bf(r10, r11);
            pl[3] = pack2bf(r12, r13);

            uint32_t vbase = (uint32_t)(js * 16 * AT_ROWB) + voff;
#pragma unroll
            for (int dp = 0; dp < 8; dp++) {
                uint32_t vh4[4], vl4[4];
                ldm_x4_trans(vh4, V_u + vbase + dp * 32);
                mma_bf16(o[2 * dp],     ph, vh4);
                mma_bf16(o[2 * dp + 1], ph, vh4 + 2);
                mma_bf16(o[2 * dp],     pl, vh4);
                mma_bf16(o[2 * dp + 1], pl, vh4 + 2);
                ldm_x4_trans(vl4, V_u + vbase + 256 + dp * 32);
                mma_bf16(o[2 * dp],     ph, vl4);
                mma_bf16(o[2 * dp + 1], ph, vl4 + 2);
            }
        }

        __syncthreads();                       // all warps done reading V
        if (knext < khi) issueTile(V_u, g_v2, knext, khi);
        CP_COMMIT();
    }

    // ---- epilogue: write split bf16 (hi | lo) into g_Actx [m][2K]
    float inv0 = 1.0f / fmaxf(l0, 1e-30f);
    float inv1 = 1.0f / fmaxf(l1, 1e-30f);
    const int cb = h * HDIM + (lane & 3) * 2;
    __nv_bfloat16* row0 = g_Actx + (size_t)r0g * K2;
    __nv_bfloat16* row1 = g_Actx + (size_t)r1g * K2;
#pragma unroll
    for (int nt = 0; nt < 16; nt++) {
        int k = cb + nt * 8;
        float v00 = o[nt][0] * inv0, v01 = o[nt][1] * inv0;
        float v10 = o[nt][2] * inv1, v11 = o[nt][3] * inv1;
        float h00 = __bfloat162float(__float2bfloat16(v00));
        float h01 = __bfloat162float(__float2bfloat16(v01));
        float h10 = __bfloat162float(__float2bfloat16(v10));
        float h11 = __bfloat162float(__float2bfloat16(v11));
        *(uint32_t*)(row0 + k)         = pack2bf(v00, v01);
        *(uint32_t*)(row0 + EMBED + k) = pack2bf(v00 - h00, v01 - h01);
        *(uint32_t*)(row1 + k)         = pack2bf(v10, v11);
        *(uint32_t*)(row1 + EMBED + k) = pack2bf(v10 - h10, v11 - h11);
    }
}

// ============================================================================
// launch
// ============================================================================
extern "C" void kernel_launch(void* const* d_in, const int* in_sizes, int n_in,
                              void* d_out, int out_size)
{
    const float* x      = (const float*)d_in[0];
    const int*   cu     = (const int*)  d_in[1];
    const float* cosb   = (const float*)d_in[2];
    const float* sinb   = (const float*)d_in[3];
    const float* w_qkv  = (const float*)d_in[4];
    const float* b_qkv  = (const float*)d_in[5];
    const float* qw     = (const float*)d_in[6];
    const float* kw     = (const float*)d_in[7];
    const float* w_proj = (const float*)d_in[8];
    const float* b_proj = (const float*)d_in[9];
    float* out = (float*)d_out;
    const int ncu = in_sizes[1];

    float* qkv_p;
    __nv_bfloat16 *Ax_p, *Actx_p, *Wtqkv_p, *Wtprj_p;
    cudaGetSymbolAddress((void**)&qkv_p,   g_qkv);
    cudaGetSymbolAddress((void**)&Ax_p,    g_Ax);
    cudaGetSymbolAddress((void**)&Actx_p,  g_Actx);
    cudaGetSymbolAddress((void**)&Wtqkv_p, g_Wtqkv);
    cudaGetSymbolAddress((void**)&Wtprj_p, g_Wtprj);

    cudaFuncSetAttribute(attn_mma, cudaFuncAttributeMaxDynamicSharedMemorySize, AT_SMEM_B);
    cudaFuncSetAttribute(gemm_mma, cudaFuncAttributeMaxDynamicSharedMemorySize, MM_SMEM);

    // split conversions (hi|lo 2K layouts)
    conv_split_A<<<(SEQ * EMBED / 4 + 255) / 256, 256>>>(x, Ax_p, SEQ, EMBED);
    conv_split_Wt<<<dim3(EMBED / 32, QKV_N / 32), dim3(32, 8)>>>(w_qkv, Wtqkv_p, EMBED, QKV_N);
    conv_split_Wt<<<dim3(EMBED / 32, EMBED / 32), dim3(32, 8)>>>(w_proj, Wtprj_p, EMBED, EMBED);

    // 1) QKV = x @ w_qkv + b_qkv
    gemm_mma<<<dim3(QKV_N / MM_BN, SEQ / MM_BM), 128, MM_SMEM>>>(Ax_p, Wtqkv_p, b_qkv, qkv_p, QKV_N, EMBED);

    // 2) RMSNorm + RoPE + hi/lo split (merged layout)
    norm_rope_split<<<dim3(SEQ, NHEADS), 128>>>(cosb, sinb, qw, kw);

    // 3) tensor-core flash attention BQ=64 (writes split proj input directly)
    attn_mma<<<dim3(SEQ / 64, NHEADS), 128, AT_SMEM_B>>>(cu, ncu);

    // 4) out = ctx @ w_proj + b_proj
    gemm_mma<<<dim3(EMBED / MM_BN, SEQ / MM_BM), 128, MM_SMEM>>>(Actx_p, Wtprj_p, b_proj, out, EMBED, EMBED);
}

// round 17
// speedup vs baseline: 1.4361x; 1.0039x over previous
#include <cuda_runtime.h>
#include <cuda_bf16.h>
#include <math.h>
#include <stdint.h>

#define SEQ       2048
#define EMBED     1536
#define NHEADS    12
#define HDIM      128
#define QKV_N     (3 * EMBED)         // 4608
#define K2        (2 * EMBED)         // hi|lo layout width = 3072
#define D2        (HDIM / 2)          // 64
#define EPS       1e-5f
// 1/sqrt(128) * log2(e)  (scores kept in log2 domain; exp2 in softmax)
#define ATT_SCL2  0.12751879524622723f

// ---------------- scratch (device globals) ----------------
__device__ float g_qkv[SEQ * QKV_N];                    // [s][3E] fp32
__device__ __nv_bfloat16 g_Ax   [SEQ * K2];             // x split   [m][hi|lo]
__device__ __nv_bfloat16 g_Actx [SEQ * K2];             // ctx split [m][hi|lo] (written by attn)
__device__ __nv_bfloat16 g_Wtqkv[QKV_N * K2];           // W_qkv^T split  (N x 2K)
__device__ __nv_bfloat16 g_Wtprj[EMBED * K2];           // W_proj^T split (N x 2K)
// attention operands merged hi|lo: [h][s][256] (hi at d, lo at 128+d)
__device__ __nv_bfloat16 g_q2[NHEADS * SEQ * 2 * HDIM];
__device__ __nv_bfloat16 g_k2[NHEADS * SEQ * 2 * HDIM];
__device__ __nv_bfloat16 g_v2[NHEADS * SEQ * 2 * HDIM];

// ============================================================================
// helpers
// ============================================================================
__device__ __forceinline__ uint32_t smem_to_u32(const void* p) {
    uint32_t a;
    asm("{ .reg .u64 t; cvta.to.shared.u64 t, %1; cvt.u32.u64 %0, t; }" : "=r"(a) : "l"(p));
    return a;
}
#define CP_ASYNC16(saddr, gptr) \
    asm volatile("cp.async.cg.shared.global [%0], [%1], 16;" \
        :: "r"(saddr), "l"(gptr) : "memory")
#define CP_COMMIT() asm volatile("cp.async.commit_group;" ::: "memory")
#define CP_WAIT1()  asm volatile("cp.async.wait_group 1;" ::: "memory")

__device__ __forceinline__ void ldm_x4(uint32_t* r, uint32_t addr) {
    asm volatile("ldmatrix.sync.aligned.m8n8.x4.shared.b16 {%0,%1,%2,%3}, [%4];"
        : "=r"(r[0]), "=r"(r[1]), "=r"(r[2]), "=r"(r[3]) : "r"(addr));
}
__device__ __forceinline__ void ldm_x4_trans(uint32_t* r, uint32_t addr) {
    asm volatile("ldmatrix.sync.aligned.m8n8.x4.trans.shared.b16 {%0,%1,%2,%3}, [%4];"
        : "=r"(r[0]), "=r"(r[1]), "=r"(r[2]), "=r"(r[3]) : "r"(addr));
}
__device__ __forceinline__ void mma_bf16(float* d, const uint32_t* a, const uint32_t* b) {
    asm volatile(
        "mma.sync.aligned.m16n8k16.row.col.f32.bf16.bf16.f32 "
        "{%0,%1,%2,%3}, {%4,%5,%6,%7}, {%8,%9}, {%0,%1,%2,%3};"
        : "+f"(d[0]), "+f"(d[1]), "+f"(d[2]), "+f"(d[3])
        : "r"(a[0]), "r"(a[1]), "r"(a[2]), "r"(a[3]), "r"(b[0]), "r"(b[1]));
}
__device__ __forceinline__ uint32_t pack2bf(float lo, float hi) {
    __nv_bfloat162 t = __floats2bfloat162_rn(lo, hi);
    return *(uint32_t*)&t;
}

// ============================================================================
// Split-bf16 conversion kernels (hi|lo 2K layouts)
// ============================================================================
__global__ __launch_bounds__(256) void conv_split_A(
    const float* __restrict__ src, __nv_bfloat16* __restrict__ dst, int M, int K)
{
    int idx = (blockIdx.x * 256 + threadIdx.x) * 4;
    if (idx >= M * K) return;
    int m = idx / K, k = idx - m * K;
    float4 x = *(const float4*)(src + idx);
    float h0 = __bfloat162float(__float2bfloat16(x.x));
    float h1 = __bfloat162float(__float2bfloat16(x.y));
    float h2 = __bfloat162float(__float2bfloat16(x.z));
    float h3 = __bfloat162float(__float2bfloat16(x.w));
    __nv_bfloat16* row = dst + (size_t)m * (2 * K);
    *(uint2*)(row + k)     = make_uint2(pack2bf(x.x, x.y), pack2bf(x.z, x.w));
    *(uint2*)(row + K + k) = make_uint2(pack2bf(x.x - h0, x.y - h1), pack2bf(x.z - h2, x.w - h3));
}

__global__ __launch_bounds__(256) void conv_split_Wt(
    const float* __restrict__ W, __nv_bfloat16* __restrict__ Wt, int K, int N)
{
    __shared__ float tile[32][33];
    int k0 = blockIdx.x * 32, n0 = blockIdx.y * 32;
    int tx = threadIdx.x, ty = threadIdx.y;   // block (32, 8)
#pragma unroll
    for (int r = 0; r < 32; r += 8)
        tile[ty + r][tx] = W[(size_t)(k0 + ty + r) * N + n0 + tx];
    __syncthreads();
#pragma unroll
    for (int r = 0; r < 32; r += 8) {
        int n = n0 + ty + r, k = k0 + tx;
        float x  = tile[tx][ty + r];
        __nv_bfloat16 hi = __float2bfloat16(x);
        __nv_bfloat16 lo = __float2bfloat16(x - __bfloat162float(hi));
        __nv_bfloat16* row = Wt + (size_t)n * (2 * K);
        row[k]     = hi;
        row[K + k] = lo;
    }
}

// ============================================================================
// mma.sync GEMM v5 (shared-operand split): C = A @ Bt^T + bias
// CTA 128x128, 4 warps (64x64), BK=32 hi|lo chunks, 3-stage cp.async ring.
// ============================================================================
#define MM_BM     128
#define MM_BN     128
#define MM_PADB   144
#define MM_TILEB  (128 * MM_PADB)            // 18432
#define MM_STAGEB (2 * MM_TILEB)             // 36864
#define MM_STAGES 3
#define MM_SMEM   (MM_STAGES * MM_STAGEB)    // 110592

__device__ __forceinline__ void mm_load_tile(
    const __nv_bfloat16* __restrict__ src, int row0, int kk, int chunk,
    uint32_t dstBase, int tid)
{
#pragma unroll
    for (int c2 = 0; c2 < 8; c2++) {
        int idx = c2 * 128 + tid;
        int row = idx >> 3;
        int c16 = idx & 7;           // 0..3 hi, 4..7 lo
        const char* gb = (const char*)(src + (size_t)(row0 + row) * (2 * kk));
        const char* g  = (c16 < 4)
            ? gb + chunk * 64 + c16 * 16
            : gb + (size_t)kk * 2 + chunk * 64 + (c16 - 4) * 16;
        CP_ASYNC16(dstBase + (uint32_t)(row * MM_PADB + c16 * 16), g);
    }
}

__global__ __launch_bounds__(128, 2) void gemm_mma(
    const __nv_bfloat16* __restrict__ A, const __nv_bfloat16* __restrict__ Bt,
    const float* __restrict__ bias, float* __restrict__ C, int N, int kk)
{
    extern __shared__ char mmsm[];
    const uint32_t S_u = smem_to_u32(mmsm);

    const int tid    = threadIdx.x;
    const int lane   = tid & 31;
    const int wid    = tid >> 5;
    const int warp_m = wid & 1;
    const int warp_n = wid >> 1;
    const int m0 = blockIdx.y * MM_BM;
    const int n0 = blockIdx.x * MM_BN;
    const int nchunk = kk / 32;        // 48

    float acc[4][8][4];
#pragma unroll
    for (int mt = 0; mt < 4; mt++)
#pragma unroll
        for (int nt = 0; nt < 8; nt++)
#pragma unroll
            for (int q = 0; q < 4; q++) acc[mt][nt][q] = 0.f;

    const uint32_t aFrag = (uint32_t)((warp_m * 64 + (lane & 15)) * MM_PADB + (lane >> 4) * 16);
    const uint32_t bFrag = (uint32_t)((warp_n * 64 + ((lane >> 4) << 3) + (lane & 7)) * MM_PADB
                                      + ((lane >> 3) & 1) * 16);

    mm_load_tile(A,  m0, kk, 0, S_u,             tid);
    mm_load_tile(Bt, n0, kk, 0, S_u + MM_TILEB,  tid);
    CP_COMMIT();
    mm_load_tile(A,  m0, kk, 1, S_u + MM_STAGEB,            tid);
    mm_load_tile(Bt, n0, kk, 1, S_u + MM_STAGEB + MM_TILEB, tid);
    CP_COMMIT();

    int slot = 0;
    for (int c = 0; c < nchunk; ++c) {
        CP_WAIT1();
        __syncthreads();
        if (c + 2 < nchunk) {
            int ns = slot + 2; if (ns >= MM_STAGES) ns -= MM_STAGES;
            mm_load_tile(A,  m0, kk, c + 2, S_u + ns * MM_STAGEB,            tid);
            mm_load_tile(Bt, n0, kk, c + 2, S_u + ns * MM_STAGEB + MM_TILEB, tid);
        }
        CP_COMMIT();

        const uint32_t Au = S_u + slot * MM_STAGEB;
        const uint32_t Bu = Au + MM_TILEB;
#pragma unroll
        for (int ks = 0; ks < 2; ++ks) {
            uint32_t ah[4][4], bh[4][4], xl[4][4];
#pragma unroll
            for (int mt = 0; mt < 4; mt++)
                ldm_x4(ah[mt], Au + aFrag + mt * 16 * MM_PADB + ks * 32);
#pragma unroll
            for (int p = 0; p < 4; p++)
                ldm_x4(bh[p], Bu + bFrag + p * 16 * MM_PADB + ks * 32);
#pragma unroll
            for (int mt = 0; mt < 4; mt++)
#pragma unroll
                for (int p = 0; p < 4; p++) {
                    mma_bf16(acc[mt][2 * p],     ah[mt], bh[p]);
                    mma_bf16(acc[mt][2 * p + 1], ah[mt], bh[p] + 2);
                }
#pragma unroll
            for (int p = 0; p < 4; p++)
                ldm_x4(xl[p], Bu + bFrag + p * 16 * MM_PADB + 64 + ks * 32);
#pragma unroll
            for (int mt = 0; mt < 4; mt++)
#pragma unroll
                for (int p = 0; p < 4; p++) {
                    mma_bf16(acc[mt][2 * p],     ah[mt], xl[p]);
                    mma_bf16(acc[mt][2 * p + 1], ah[mt], xl[p] + 2);
                }
#pragma unroll
            for (int mt = 0; mt < 4; mt++)
                ldm_x4(xl[mt], Au + aFrag + mt * 16 * MM_PADB + 64 + ks * 32);
#pragma unroll
            for (int mt = 0; mt < 4; mt++)
#pragma unroll
                for (int p = 0; p < 4; p++) {
                    mma_bf16(acc[mt][2 * p],     xl[mt], bh[p]);
                    mma_bf16(acc[mt][2 * p + 1], xl[mt], bh[p] + 2);
                }
        }
        slot++; if (slot >= MM_STAGES) slot = 0;
    }

    const int erow = lane >> 2;
    const int ecol = (lane & 3) * 2;
#pragma unroll
    for (int mt = 0; mt < 4; mt++) {
        int row = m0 + warp_m * 64 + mt * 16 + erow;
#pragma unroll
        for (int nt = 0; nt < 8; nt++) {
            int col = n0 + warp_n * 64 + nt * 8 + ecol;
            float b0 = bias[col], b1 = bias[col + 1];
            float* c0 = C + (size_t)row * N + col;
            float* c1 = C + (size_t)(row + 8) * N + col;
            c0[0] = acc[mt][nt][0] + b0;
            c0[1] = acc[mt][nt][1] + b1;
            c1[0] = acc[mt][nt][2] + b0;
            c1[1] = acc[mt][nt][3] + b1;
        }
    }
}

// ============================================================================
// RMSNorm + RoPE + hi/lo split into merged [h][s][256] layout
// ============================================================================
__global__ __launch_bounds__(128) void norm_rope_split(
    const float* __restrict__ cosb, const float* __restrict__ sinb,
    const float* __restrict__ qw,   const float* __restrict__ kw)
{
    const int s = blockIdx.x, h = blockIdx.y, d = threadIdx.x;
    __shared__ float sh[128];
    __shared__ float wsum[4];
    __shared__ float rms_sh;

    const float* base = g_qkv + (size_t)s * QKV_N + h * HDIM;
    const int d2 = (d < D2) ? d : d - D2;
    const float c  = cosb[s * D2 + d2];
    const float sn = sinb[s * D2 + d2];
    const size_t o2 = ((size_t)h * SEQ + s) * (2 * HDIM) + d;

#pragma unroll
    for (int which = 0; which < 2; which++) {
        const float x = base[which * EMBED + d];
        float v = x * x;
#pragma unroll
        for (int o = 16; o; o >>= 1) v += __shfl_xor_sync(0xffffffffu, v, o);
        if ((d & 31) == 0) wsum[d >> 5] = v;
        __syncthreads();
        if (d == 0)
            rms_sh = rsqrtf((wsum[0] + wsum[1] + wsum[2] + wsum[3]) * (1.0f / HDIM) + EPS);
        __syncthreads();
        const float* w = which ? kw : qw;
        sh[d] = x * rms_sh * w[d];
        __syncthreads();
        float out;
        if (d < D2) out = sh[d] * c - sh[d + D2] * sn;
        else        out = sh[d] * c + sh[d - D2] * sn;
        __nv_bfloat16 hi = __float2bfloat16(out);
        __nv_bfloat16 lo = __float2bfloat16(out - __bfloat162float(hi));
        if (which == 0) { g_q2[o2] = hi; g_q2[o2 + HDIM] = lo; }
        else            { g_k2[o2] = hi; g_k2[o2 + HDIM] = lo; }
        __syncthreads();
    }
    float v = base[2 * EMBED + d];
    __nv_bfloat16 vh = __float2bfloat16(v);
    g_v2[o2]        = vh;
    g_v2[o2 + HDIM] = __float2bfloat16(v - __bfloat162float(vh));
}

// ============================================================================
// tensor-core flash attention (BQ=64, uniform fast path + exp2)
// tiles: 64 rows x 528B (256B hi | 256B lo | 16B pad)
// ============================================================================
#define AT_ROWB  528
#define AT_TILEB (64 * AT_ROWB)          // 33792
#define AT_SMEM_B (3 * AT_TILEB)         // 101376

__global__ __launch_bounds__(128) void attn_mma(const int* __restrict__ cu, int ncu)
{
    extern __shared__ char at_smem[];
    const uint32_t S_u = smem_to_u32(at_smem);
    const uint32_t Q_u = S_u;
    const uint32_t K_u = S_u + AT_TILEB;
    const uint32_t V_u = S_u + 2 * AT_TILEB;
    __shared__ int scu[16];

    const int h    = blockIdx.y;
    const int q0   = blockIdx.x * 64;
    const int tid  = threadIdx.x;
    const int warp = tid >> 5;
    const int lane = tid & 31;

    const size_t hb = (size_t)h * SEQ * (2 * HDIM);

    auto issueTile = [&](uint32_t dst, const __nv_bfloat16* src, int kb, int khi) {
#pragma unroll
        for (int c = 0; c < 16; c++) {
            int i = c * 128 + tid;
            int row = i >> 5, ch = (i & 31) * 16;
            int gr = kb + row; if (gr > khi - 1) gr = khi - 1;
            CP_ASYNC16(dst + (uint32_t)(row * AT_ROWB + ch),
                       (const char*)(src + hb + (size_t)gr * (2 * HDIM)) + ch);
        }
    };

    if (tid < ncu && tid < 16) scu[tid] = cu[tid];
    __syncthreads();

    auto seg = [&](int p) {
        int sgi = 0;
        for (int i = 1; i < ncu; i++) sgi += (scu[i] <= p) ? 1 : 0;
        return sgi;
    };
    int klo, khi;
    bool qUniform;
    {
        int s0 = seg(q0), s1 = seg(q0 + 63);
        qUniform = (s0 == s1);
        if (qUniform) { klo = scu[s0]; khi = scu[s0 + 1]; }
        else          { klo = 0;       khi = SEQ; }
    }

    // prologue: group0 = Q + K(klo); group1 = V(klo)
    issueTile(Q_u, g_q2, q0, q0 + 64);
    issueTile(K_u, g_k2, klo, khi);
    CP_COMMIT();
    issueTile(V_u, g_v2, klo, khi);
    CP_COMMIT();

    const int rloc  = lane >> 2;
    const int r0g   = q0 + warp * 16 + rloc;
    const int r1g   = r0g + 8;
    const int sq0   = seg(r0g), sq1 = seg(r1g);

    float m0 = -1e30f, m1 = -1e30f, l0 = 0.f, l1 = 0.f;
    float o[16][4];
#pragma unroll
    for (int nt = 0; nt < 16; nt++)
#pragma unroll
        for (int q = 0; q < 4; q++) o[nt][q] = 0.f;

    const uint32_t aoff = (uint32_t)((warp * 16 + (lane & 15)) * AT_ROWB + ((lane >> 4) * 8) * 2);
    const uint32_t boff = (uint32_t)(((lane & 7) + ((lane >> 4) << 3)) * AT_ROWB + (((lane >> 3) & 1) * 8) * 2);
    const uint32_t voff = (uint32_t)((((lane >> 3) & 1) * 8 + (lane & 7)) * AT_ROWB + ((lane >> 4) * 8) * 2);

    // Q resident after first wait; preload all Q fragments (hi+lo) into registers
    CP_WAIT1();
    __syncthreads();
    uint32_t qh[8][4], ql[8][4];
#pragma unroll
    for (int ks = 0; ks < 8; ks++) {
        ldm_x4(qh[ks], Q_u + aoff + ks * 32);
        ldm_x4(ql[ks], Q_u + aoff + 256 + ks * 32);
    }

    for (int kb = klo; kb < khi; kb += 64) {
        const int knext = kb + 64;
        const bool full = qUniform && (knext <= khi);   // no masking needed

        CP_WAIT1();          // K(kb) resident
        __syncthreads();

        // ---- S = scl2 * (Qh Kh^T + Ql Kh^T + Qh Kl^T)   (log2 domain)
        float s[8][4];
#pragma unroll
        for (int nt = 0; nt < 8; nt++)
#pragma unroll
            for (int q = 0; q < 4; q++) s[nt][q] = 0.f;

#pragma unroll
        for (int ks = 0; ks < 8; ks++) {
            uint32_t kf[4][4];
#pragma unroll
            for (int np = 0; np < 4; np++)
                ldm_x4(kf[np], K_u + boff + np * 16 * AT_ROWB + ks * 32);
#pragma unroll
            for (int np = 0; np < 4; np++) {
                mma_bf16(s[2 * np],     qh[ks], kf[np]);
                mma_bf16(s[2 * np + 1], qh[ks], kf[np] + 2);
                mma_bf16(s[2 * np],     ql[ks], kf[np]);
                mma_bf16(s[2 * np + 1], ql[ks], kf[np] + 2);
            }
#pragma unroll
            for (int np = 0; np < 4; np++)
                ldm_x4(kf[np], K_u + boff + np * 16 * AT_ROWB + 256 + ks * 32);
#pragma unroll
            for (int np = 0; np < 4; np++) {
                mma_bf16(s[2 * np],     qh[ks], kf[np]);
                mma_bf16(s[2 * np + 1], qh[ks], kf[np] + 2);
            }
        }

        __syncthreads();                       // all warps done reading K
        if (knext < khi) issueTile(K_u, g_k2, knext, khi);
        CP_COMMIT();

        // ---- scale (+ segment mask only when needed)
        if (full) {
#pragma unroll
            for (int nt = 0; nt < 8; nt++) {
                s[nt][0] *= ATT_SCL2; s[nt][1] *= ATT_SCL2;
                s[nt][2] *= ATT_SCL2; s[nt][3] *= ATT_SCL2;
            }
        } else {
#pragma unroll
            for (int nt = 0; nt < 8; nt++) {
                int j0 = kb + nt * 8 + (lane & 3) * 2;
                int j1 = j0 + 1;
                int sk0 = (j0 < khi) ? seg(j0) : -1;
                int sk1 = (j1 < khi) ? seg(j1) : -1;
                s[nt][0] = (sk0 == sq0) ? s[nt][0] * ATT_SCL2 : -1e30f;
                s[nt][1] = (sk1 == sq0) ? s[nt][1] * ATT_SCL2 : -1e30f;
                s[nt][2] = (sk0 == sq1) ? s[nt][2] * ATT_SCL2 : -1e30f;
                s[nt][3] = (sk1 == sq1) ? s[nt][3] * ATT_SCL2 : -1e30f;
            }
        }

        // ---- online softmax (exp2; branch-free in the full path)
        float mx0 = -1e30f, mx1 = -1e30f;
#pragma unroll
        for (int nt = 0; nt < 8; nt++) {
            mx0 = fmaxf(mx0, fmaxf(s[nt][0], s[nt][1]));
            mx1 = fmaxf(mx1, fmaxf(s[nt][2], s[nt][3]));
        }
        mx0 = fmaxf(mx0, __shfl_xor_sync(0xffffffffu, mx0, 1));
        mx0 = fmaxf(mx0, __shfl_xor_sync(0xffffffffu, mx0, 2));
        mx1 = fmaxf(mx1, __shfl_xor_sync(0xffffffffu, mx1, 1));
        mx1 = fmaxf(mx1, __shfl_xor_sync(0xffffffffu, mx1, 2));
        float mn0 = fmaxf(m0, mx0), mn1 = fmaxf(m1, mx1);
        float a0, a1, ls0 = 0.f, ls1 = 0.f;
        if (full) {
            a0 = exp2f(m0 - mn0);
            a1 = exp2f(m1 - mn1);
#pragma unroll
            for (int nt = 0; nt < 8; nt++) {
                float p0 = exp2f(s[nt][0] - mn0);
                float p1 = exp2f(s[nt][1] - mn0);
                float p2 = exp2f(s[nt][2] - mn1);
                float p3 = exp2f(s[nt][3] - mn1);
                s[nt][0] = p0; s[nt][1] = p1; s[nt][2] = p2; s[nt][3] = p3;
                ls0 += p0 + p1; ls1 += p2 + p3;
            }
        } else {
            bool live0 = mn0 > -1e29f, live1 = mn1 > -1e29f;
            a0 = live0 ? exp2f(m0 - mn0) : 1.f;
            a1 = live1 ? exp2f(m1 - mn1) : 1.f;
#pragma unroll
            for (int nt = 0; nt < 8; nt++) {
                float p0 = live0 ? exp2f(s[nt][0] - mn0) : 0.f;
                float p1 = live0 ? exp2f(s[nt][1] - mn0) : 0.f;
                float p2 = live1 ? exp2f(s[nt][2] - mn1) : 0.f;
                float p3 = live1 ? exp2f(s[nt][3] - mn1) : 0.f;
                s[nt][0] = p0; s[nt][1] = p1; s[nt][2] = p2; s[nt][3] = p3;
                ls0 += p0 + p1; ls1 += p2 + p3;
            }
        }
        ls0 += __shfl_xor_sync(0xffffffffu, ls0, 1);
        ls0 += __shfl_xor_sync(0xffffffffu, ls0, 2);
        ls1 += __shfl_xor_sync(0xffffffffu, ls1, 1);
        ls1 += __shfl_xor_sync(0xffffffffu, ls1, 2);
        l0 = l0 * a0 + ls0;  l1 = l1 * a1 + ls1;
        m0 = mn0;  m1 = mn1;

#pragma unroll
        for (int nt = 0; nt < 16; nt++) {
            o[nt][0] *= a0; o[nt][1] *= a0;
            o[nt][2] *= a1; o[nt][3] *= a1;
        }

        CP_WAIT1();          // V(kb) resident (pending: K(knext))
        __syncthreads();

        // ---- O += Ph Vh + Pl Vh + Ph Vl
#pragma unroll
        for (int js = 0; js < 4; js++) {
            float* t0 = s[2 * js];
            float* t1 = s[2 * js + 1];
            uint32_t ph[4], pl[4];
            ph[0] = pack2bf(t0[0], t0[1]);
            ph[1] = pack2bf(t0[2], t0[3]);
            ph[2] = pack2bf(t1[0], t1[1]);
            ph[3] = pack2bf(t1[2], t1[3]);
            float r00 = t0[0] - __bfloat162float(__float2bfloat16(t0[0]));
            float r01 = t0[1] - __bfloat162float(__float2bfloat16(t0[1]));
            float r02 = t0[2] - __bfloat162float(__float2bfloat16(t0[2]));
            float r03 = t0[3] - __bfloat162float(__float2bfloat16(t0[3]));
            float r10 = t1[0] - __bfloat162float(__float2bfloat16(t1[0]));
            float r11 = t1[1] - __bfloat162float(__float2bfloat16(t1[1]));
            float r12 = t1[2] - __bfloat162float(__float2bfloat16(t1[2]));
            float r13 = t1[3] - __bfloat162float(__float2bfloat16(t1[3]));
            pl[0] = pack2bf(r00, r01);
            pl[1] = pack2bf(r02, r03);
            pl[2] = pack2bf(r10, r11);
            pl[3] = pack2bf(r12, r13);

            uint32_t vbase = (uint32_t)(js * 16 * AT_ROWB) + voff;
#pragma unroll
            for (int dp = 0; dp < 8; dp++) {
                uint32_t vh4[4], vl4[4];
                ldm_x4_trans(vh4, V_u + vbase + dp * 32);
                mma_bf16(o[2 * dp],     ph, vh4);
                mma_bf16(o[2 * dp + 1], ph, vh4 + 2);
                mma_bf16(o[2 * dp],     pl, vh4);
                mma_bf16(o[2 * dp + 1], pl, vh4 + 2);
                ldm_x4_trans(vl4, V_u + vbase + 256 + dp * 32);
                mma_bf16(o[2 * dp],     ph, vl4);
                mma_bf16(o[2 * dp + 1], ph, vl4 + 2);
            }
        }

        __syncthreads();                       // all warps done reading V
        if (knext < khi) issueTile(V_u, g_v2, knext, khi);
        CP_COMMIT();
    }

    // ---- epilogue: write split bf16 (hi | lo) into g_Actx [m][2K]
    float inv0 = 1.0f / fmaxf(l0, 1e-30f);
    float inv1 = 1.0f / fmaxf(l1, 1e-30f);
    const int cb = h * HDIM + (lane & 3) * 2;
    __nv_bfloat16* row0 = g_Actx + (size_t)r0g * K2;
    __nv_bfloat16* row1 = g_Actx + (size_t)r1g * K2;
#pragma unroll
    for (int nt = 0; nt < 16; nt++) {
        int k = cb + nt * 8;
        float v00 = o[nt][0] * inv0, v01 = o[nt][1] * inv0;
        float v10 = o[nt][2] * inv1, v11 = o[nt][3] * inv1;
        float h00 = __bfloat162float(__float2bfloat16(v00));
        float h01 = __bfloat162float(__float2bfloat16(v01));
        float h10 = __bfloat162float(__float2bfloat16(v10));
        float h11 = __bfloat162float(__float2bfloat16(v11));
        *(uint32_t*)(row0 + k)         = pack2bf(v00, v01);
        *(uint32_t*)(row0 + EMBED + k) = pack2bf(v00 - h00, v01 - h01);
        *(uint32_t*)(row1 + k)         = pack2bf(v10, v11);
        *(uint32_t*)(row1 + EMBED + k) = pack2bf(v10 - h10, v11 - h11);
    }
}

// ============================================================================
// launch
// ============================================================================
extern "C" void kernel_launch(void* const* d_in, const int* in_sizes, int n_in,
                              void* d_out, int out_size)
{
    const float* x      = (const float*)d_in[0];
    const int*   cu     = (const int*)  d_in[1];
    const float* cosb   = (const float*)d_in[2];
    const float* sinb   = (const float*)d_in[3];
    const float* w_qkv  = (const float*)d_in[4];
    const float* b_qkv  = (const float*)d_in[5];
    const float* qw     = (const float*)d_in[6];
    const float* kw     = (const float*)d_in[7];
    const float* w_proj = (const float*)d_in[8];
    const float* b_proj = (const float*)d_in[9];
    float* out = (float*)d_out;
    const int ncu = in_sizes[1];

    float* qkv_p;
    __nv_bfloat16 *Ax_p, *Actx_p, *Wtqkv_p, *Wtprj_p;
    cudaGetSymbolAddress((void**)&qkv_p,   g_qkv);
    cudaGetSymbolAddress((void**)&Ax_p,    g_Ax);
    cudaGetSymbolAddress((void**)&Actx_p,  g_Actx);
    cudaGetSymbolAddress((void**)&Wtqkv_p, g_Wtqkv);
    cudaGetSymbolAddress((void**)&Wtprj_p, g_Wtprj);

    cudaFuncSetAttribute(attn_mma, cudaFuncAttributeMaxDynamicSharedMemorySize, AT_SMEM_B);
    cudaFuncSetAttribute(gemm_mma, cudaFuncAttributeMaxDynamicSharedMemorySize, MM_SMEM);

    // split conversions (hi|lo 2K layouts)
    conv_split_A<<<(SEQ * EMBED / 4 + 255) / 256, 256>>>(x, Ax_p, SEQ, EMBED);
    conv_split_Wt<<<dim3(EMBED / 32, QKV_N / 32), dim3(32, 8)>>>(w_qkv, Wtqkv_p, EMBED, QKV_N);
    conv_split_Wt<<<dim3(EMBED / 32, EMBED / 32), dim3(32, 8)>>>(w_proj, Wtprj_p, EMBED, EMBED);

    // 1) QKV = x @ w_qkv + b_qkv
    gemm_mma<<<dim3(QKV_N / MM_BN, SEQ / 128), 128, MM_SMEM>>>(Ax_p, Wtqkv_p, b_qkv, qkv_p, QKV_N, EMBED);

    // 2) RMSNorm + RoPE + hi/lo split (merged layout)
    norm_rope_split<<<dim3(SEQ, NHEADS), 128>>>(cosb, sinb, qw, kw);

    // 3) tensor-core flash attention BQ=64 (writes split proj input directly)
    attn_mma<<<dim3(SEQ / 64, NHEADS), 128, AT_SMEM_B>>>(cu, ncu);

    // 4) out = ctx @ w_proj + b_proj
    gemm_mma<<<dim3(EMBED / MM_BN, SEQ / 128), 128, MM_SMEM>>>(Actx_p, Wtprj_p, b_proj, out, EMBED, EMBED);
}